// round 3
// baseline (speedup 1.0000x reference)
#include <cuda_runtime.h>
#include <math.h>

#define B_ 16
#define N_ 1024
#define D_ 128
#define L_ 4
#define ND ((size_t)B_*N_*D_)
#define NN1 ((size_t)N_*N_)
#define ND1 ((size_t)N_*D_)

__device__ __align__(128) float g_h [B_*N_*D_];
__device__ __align__(128) float g_hh[B_*N_*D_];
__device__ __align__(128) float g_hA[B_*N_*D_];
__device__ __align__(128) float g_az[B_*N_*D_];
__device__ __align__(128) float g_zA[B_*N_*D_];
__device__ __align__(128) float g_zB[B_*N_*D_];
__device__ __align__(128) float g_zC[B_*N_*D_];
__device__ __align__(128) float g_zD[B_*N_*D_];
__device__ __align__(128) float g_att[B_*N_*N_];
__device__ __align__(128) float g_m [B_*N_];
__device__ __align__(128) float g_is[B_*N_];
__device__ __align__(128) float g_cf[B_*N_];
__device__ __align__(128) float g_pool[B_*D_];

// ---- SGEMM 128x128 tile, 8x8/thread. EPI: 0 none,1 +bias,2 relu,3 hop ----
template<bool TRANSB, int EPI>
__global__ void __launch_bounds__(256, 2)
sgemm_k(const float* __restrict__ Ag, const float* __restrict__ Bg,
        float* __restrict__ Cg, int M, int Nc, int K,
        size_t strA, size_t strB, size_t strC,
        const float* __restrict__ bias,
        const float* __restrict__ coeff,
        const float* __restrict__ Hres)
{
    __shared__ float As[16][132];
    __shared__ float Bs[16][132];
    const int tid = threadIdx.x;
    const int tx = tid & 15, ty = tid >> 4;
    const int bz = blockIdx.z;
    const float* A  = Ag + strA * bz;
    const float* Bp = Bg + strB * bz;
    float*       C  = Cg + strC * bz;
    const int mbase = blockIdx.y * 128;
    const int nbase = blockIdx.x * 128;

    const int arow  = tid >> 1;
    const int akoff = (tid & 1) * 8;
    const float* aptr = A + (size_t)(mbase + arow) * K + akoff;

    int bkr = 0, bcoff = 0, bn = 0, bkh = 0;
    const float* bptr;
    if (!TRANSB) { bkr = tid >> 4; bcoff = (tid & 15) * 8;
                   bptr = Bp + (size_t)bkr * Nc + nbase + bcoff; }
    else         { bn = tid & 127; bkh = (tid >> 7) * 8;
                   bptr = Bp + (size_t)(nbase + bn) * K + bkh; }

    float acc[8][8];
#pragma unroll
    for (int i = 0; i < 8; i++)
#pragma unroll
        for (int j = 0; j < 8; j++) acc[i][j] = 0.f;

    float4 pa0 = *(const float4*)(aptr);
    float4 pa1 = *(const float4*)(aptr + 4);
    float4 pb0 = *(const float4*)(bptr);
    float4 pb1 = *(const float4*)(bptr + 4);

    const int nk = K >> 4;
    for (int kc = 0; kc < nk; ++kc) {
        As[akoff+0][arow]=pa0.x; As[akoff+1][arow]=pa0.y;
        As[akoff+2][arow]=pa0.z; As[akoff+3][arow]=pa0.w;
        As[akoff+4][arow]=pa1.x; As[akoff+5][arow]=pa1.y;
        As[akoff+6][arow]=pa1.z; As[akoff+7][arow]=pa1.w;
        if (!TRANSB) {
            *(float4*)&Bs[bkr][bcoff]   = pb0;
            *(float4*)&Bs[bkr][bcoff+4] = pb1;
        } else {
            Bs[bkh+0][bn]=pb0.x; Bs[bkh+1][bn]=pb0.y;
            Bs[bkh+2][bn]=pb0.z; Bs[bkh+3][bn]=pb0.w;
            Bs[bkh+4][bn]=pb1.x; Bs[bkh+5][bn]=pb1.y;
            Bs[bkh+6][bn]=pb1.z; Bs[bkh+7][bn]=pb1.w;
        }
        __syncthreads();
        if (kc + 1 < nk) {
            const float* ap = aptr + (kc + 1) * 16;
            pa0 = *(const float4*)ap; pa1 = *(const float4*)(ap + 4);
            const float* bp = TRANSB ? (bptr + (kc + 1) * 16)
                                     : (bptr + (size_t)(kc + 1) * 16 * Nc);
            pb0 = *(const float4*)bp; pb1 = *(const float4*)(bp + 4);
        }
#pragma unroll
        for (int kk = 0; kk < 16; ++kk) {
            float4 av0 = *(const float4*)&As[kk][ty*8];
            float4 av1 = *(const float4*)&As[kk][ty*8+4];
            float4 bv0 = *(const float4*)&Bs[kk][tx*8];
            float4 bv1 = *(const float4*)&Bs[kk][tx*8+4];
            float ar[8] = {av0.x,av0.y,av0.z,av0.w,av1.x,av1.y,av1.z,av1.w};
            float br[8] = {bv0.x,bv0.y,bv0.z,bv0.w,bv1.x,bv1.y,bv1.z,bv1.w};
#pragma unroll
            for (int i = 0; i < 8; i++)
#pragma unroll
                for (int j = 0; j < 8; j++)
                    acc[i][j] += ar[i] * br[j];
        }
        __syncthreads();
    }

    const int row0 = mbase + ty * 8;
    const int col0 = nbase + tx * 8;
#pragma unroll
    for (int i = 0; i < 8; i++) {
        const int row = row0 + i;
        float cf_ = 0.f, om_ = 0.f;
        if (EPI == 3) { cf_ = coeff[(size_t)bz * M + row]; om_ = 1.f - cf_; }
        float o[8];
#pragma unroll
        for (int j = 0; j < 8; j++) {
            float v = acc[i][j];
            if (EPI == 1) v += bias[col0 + j];
            if (EPI == 2) v = fmaxf(v, 0.f);
            if (EPI == 3) v = cf_ * Hres[strC*bz + (size_t)row*Nc + col0 + j]
                            + om_ * fmaxf(v, 0.f);
            o[j] = v;
        }
        float4* cp = (float4*)(C + (size_t)row * Nc + col0);
        cp[0] = make_float4(o[0], o[1], o[2], o[3]);
        cp[1] = make_float4(o[4], o[5], o[6], o[7]);
    }
}

// ---- e := adj>0 ? e + e^T : 0  (in-place, tile-pair safe) ----
__global__ void symmask_k(const float* __restrict__ adj, float* __restrict__ e)
{
    const int bj = blockIdx.x, bk = blockIdx.y, b = blockIdx.z;
    if (bj > bk) return;
    __shared__ float T1[32][33], T2[32][33];
    const int tx = threadIdx.x, ty = threadIdx.y;
    const size_t base = (size_t)b * NN1;
    const int j0 = bj * 32, k0 = bk * 32;
    T1[ty][tx] = e[base + (size_t)(j0+ty)*N_ + k0+tx];
    T2[ty][tx] = e[base + (size_t)(k0+ty)*N_ + j0+tx];
    __syncthreads();
    float s  = T1[ty][tx] + T2[tx][ty];
    float aj = adj[base + (size_t)(j0+ty)*N_ + k0+tx];
    e[base + (size_t)(j0+ty)*N_ + k0+tx] = (aj > 0.f) ? s : 0.f;
    if (bj != bk) {
        float s2 = T2[ty][tx] + T1[tx][ty];
        float a2 = adj[base + (size_t)(k0+ty)*N_ + j0+tx];
        e[base + (size_t)(k0+ty)*N_ + j0+tx] = (a2 > 0.f) ? s2 : 0.f;
    }
}

// ---- per-column (axis j) max & inv-sum-exp ----
__global__ void colstats_k(const float* __restrict__ att,
                           float* __restrict__ mx, float* __restrict__ isum)
{
    const int b = blockIdx.y;
    const int k = blockIdx.x * 256 + threadIdx.x;
    const float* p = att + (size_t)b * NN1 + k;
    float m = -1e30f;
    for (int j = 0; j < N_; j++) m = fmaxf(m, p[(size_t)j * N_]);
    float s = 0.f;
    for (int j = 0; j < N_; j++) s += __expf(p[(size_t)j * N_] - m);
    mx[b * N_ + k] = m;
    isum[b * N_ + k] = 1.f / s;
}

// ---- att := adj>0 ? exp(v-m)*is : 0 ----
__global__ void norm_k(const float* __restrict__ adj,
                       const float* __restrict__ mx, const float* __restrict__ isum,
                       float* __restrict__ att)
{
    const size_t i = (size_t)blockIdx.x * blockDim.x + threadIdx.x;
    const size_t e0 = i * 4;
    const int b = (int)(e0 >> 20);
    const int k = (int)(e0 & (N_ - 1));
    const int mi = b * N_ + k;
    float4 v = ((const float4*)att)[i];
    float4 a = ((const float4*)adj)[i];
    float4 o;
    o.x = (a.x > 0.f) ? __expf(v.x - mx[mi+0]) * isum[mi+0] : 0.f;
    o.y = (a.y > 0.f) ? __expf(v.y - mx[mi+1]) * isum[mi+1] : 0.f;
    o.z = (a.z > 0.f) ? __expf(v.z - mx[mi+2]) * isum[mi+2] : 0.f;
    o.w = (a.w > 0.f) ? __expf(v.w - mx[mi+3]) * isum[mi+3] : 0.f;
    ((float4*)att)[i] = o;
}

// ---- coeff = sigmoid([h,az]@gw^T + gb) : one warp per row ----
__global__ void coeff_k(const float* __restrict__ h, const float* __restrict__ az,
                        const float* __restrict__ gw, const float* __restrict__ gb,
                        float* __restrict__ cf)
{
    const int row = (blockIdx.x * blockDim.x + threadIdx.x) >> 5;
    const int lane = threadIdx.x & 31;
    if (row >= B_ * N_) return;
    const float* hp = h + (size_t)row * D_;
    const float* ap = az + (size_t)row * D_;
    float s = 0.f;
    for (int i = lane; i < D_; i += 32) s += hp[i]*gw[i] + ap[i]*gw[D_+i];
    for (int o = 16; o; o >>= 1) s += __shfl_xor_sync(0xFFFFFFFFu, s, o);
    if (lane == 0) cf[row] = 1.f / (1.f + __expf(-(s + gb[0])));
}

// ---- z = cf*h + (1-cf)*az  (az pre-relu'd) ----
__global__ void hop1_k(const float* __restrict__ h, const float* __restrict__ az,
                       const float* __restrict__ cf, float* __restrict__ z)
{
    const size_t i = (size_t)blockIdx.x * blockDim.x + threadIdx.x;
    const int row = (int)(i >> 5);           // i*4 / 128
    const float c = cf[row], om = 1.f - c;
    float4 hv = ((const float4*)h)[i];
    float4 av = ((const float4*)az)[i];
    float4 o;
    o.x = c*hv.x + om*av.x; o.y = c*hv.y + om*av.y;
    o.z = c*hv.z + om*av.z; o.w = c*hv.w + om*av.w;
    ((float4*)z)[i] = o;
}

__global__ void sub_k(const float* __restrict__ z2, const float* __restrict__ z1,
                      float* __restrict__ o)
{
    const size_t i = (size_t)blockIdx.x * blockDim.x + threadIdx.x;
    float4 a = ((const float4*)z2)[i];
    float4 b = ((const float4*)z1)[i];
    ((float4*)o)[i] = make_float4(a.x-b.x, a.y-b.y, a.z-b.z, a.w-b.w);
}

__global__ void pool_k(const float* __restrict__ h, const float* __restrict__ valid,
                       float* __restrict__ pooled)
{
    const int b = blockIdx.x, d = threadIdx.x;
    float s = 0.f, vs = 0.f;
    for (int n = 0; n < N_; n++) {
        float v = valid[b * N_ + n];
        s += h[((size_t)b * N_ + n) * D_ + d] * v;
        vs += v;
    }
    pooled[b * D_ + d] = s / vs;
}

__global__ void mlp_k(const float* __restrict__ pooled,
                      const float* __restrict__ w0, const float* __restrict__ b0,
                      const float* __restrict__ w1, const float* __restrict__ b1,
                      const float* __restrict__ w2, const float* __restrict__ b2,
                      const float* __restrict__ w3, const float* __restrict__ b3,
                      float* __restrict__ out)
{
    __shared__ float a0[128], a1[128], red[4];
    const int b = blockIdx.x, t = threadIdx.x;
    a0[t] = pooled[b * 128 + t];
    __syncthreads();
    float s = 0.f;
    for (int i = 0; i < 128; i++) s += a0[i] * w0[t*128+i];
    a1[t] = fmaxf(s + b0[t], 0.f);
    __syncthreads();
    s = 0.f;
    for (int i = 0; i < 128; i++) s += a1[i] * w1[t*128+i];
    a0[t] = fmaxf(s + b1[t], 0.f);
    __syncthreads();
    s = 0.f;
    for (int i = 0; i < 128; i++) s += a0[i] * w2[t*128+i];
    a1[t] = fmaxf(s + b2[t], 0.f);
    __syncthreads();
    float p = a1[t] * w3[t];
    for (int o = 16; o; o >>= 1) p += __shfl_xor_sync(0xFFFFFFFFu, p, o);
    if ((t & 31) == 0) red[t >> 5] = p;
    __syncthreads();
    if (t == 0) {
        float tot = red[0] + red[1] + red[2] + red[3] + b3[0];
        out[b] = 1.f / (1.f + expf(-tot));
    }
}

extern "C" void kernel_launch(void* const* d_in, const int* in_sizes, int n_in,
                              void* d_out, int out_size)
{
    const float* x       = (const float*)d_in[0];
    const float* adj1    = (const float*)d_in[1];
    const float* adj2    = (const float*)d_in[2];
    const float* valid   = (const float*)d_in[3];
    const float* embede_w= (const float*)d_in[4];
    const float* gW      = (const float*)d_in[5];
    const float* gb      = (const float*)d_in[6];
    const float* gA      = (const float*)d_in[7];
    const float* gate_w  = (const float*)d_in[8];
    const float* gate_b  = (const float*)d_in[9];
    const float* fc0_w   = (const float*)d_in[10];
    const float* fc0_b   = (const float*)d_in[11];
    const float* fc1_w   = (const float*)d_in[12];
    const float* fc1_b   = (const float*)d_in[13];
    const float* fc2_w   = (const float*)d_in[14];
    const float* fc2_b   = (const float*)d_in[15];
    const float* fc3_w   = (const float*)d_in[16];
    const float* fc3_b   = (const float*)d_in[17];
    float* out = (float*)d_out;

    float *p_h, *p_hh, *p_hA, *p_az, *p_zA, *p_zB, *p_zC, *p_zD,
          *p_att, *p_m, *p_is, *p_cf, *p_pool;
    cudaGetSymbolAddress((void**)&p_h,  g_h);
    cudaGetSymbolAddress((void**)&p_hh, g_hh);
    cudaGetSymbolAddress((void**)&p_hA, g_hA);
    cudaGetSymbolAddress((void**)&p_az, g_az);
    cudaGetSymbolAddress((void**)&p_zA, g_zA);
    cudaGetSymbolAddress((void**)&p_zB, g_zB);
    cudaGetSymbolAddress((void**)&p_zC, g_zC);
    cudaGetSymbolAddress((void**)&p_zD, g_zD);
    cudaGetSymbolAddress((void**)&p_att,g_att);
    cudaGetSymbolAddress((void**)&p_m,  g_m);
    cudaGetSymbolAddress((void**)&p_is, g_is);
    cudaGetSymbolAddress((void**)&p_cf, g_cf);
    cudaGetSymbolAddress((void**)&p_pool, g_pool);

    const int NHOPS[4] = {1, 2, 3, 4};

    // h = x @ embede_w^T
    sgemm_k<true,0><<<dim3(1,128,1),256>>>(x, embede_w, p_h,
        B_*N_, D_, D_, 0,0,0, nullptr, nullptr, nullptr);

    for (int k = 0; k < L_; k++) {
        const float* Wk  = gW + (size_t)k * D_ * D_;
        const float* bk  = gb + (size_t)k * D_;
        const float* Ak  = gA + (size_t)k * D_ * D_;
        const float* gwk = gate_w + (size_t)k * 2 * D_;
        const float* gbk = gate_b + k;
        const int nhop = NHOPS[k];
        float* zfin[2];

        for (int br = 0; br < 2; br++) {
            const float* adj = br ? adj2 : adj1;
            float* zc = br ? p_zC : p_zA;
            float* zn = br ? p_zD : p_zB;

            // hh = h @ Wk^T + bk
            sgemm_k<true,1><<<dim3(1,128,1),256>>>(p_h, Wk, p_hh,
                B_*N_, D_, D_, 0,0,0, bk, nullptr, nullptr);
            // hA = hh @ Ak
            sgemm_k<false,0><<<dim3(1,128,1),256>>>(p_hh, Ak, p_hA,
                B_*N_, D_, D_, 0,0,0, nullptr, nullptr, nullptr);
            // e = hA @ hh^T  (batched)
            sgemm_k<true,0><<<dim3(8,8,B_),256>>>(p_hA, p_hh, p_att,
                N_, N_, D_, ND1, ND1, NN1, nullptr, nullptr, nullptr);
            // symmetrize + mask
            symmask_k<<<dim3(32,32,B_), dim3(32,32)>>>(adj, p_att);
            // softmax over axis j
            colstats_k<<<dim3(4,B_),256>>>(p_att, p_m, p_is);
            norm_k<<<16384,256>>>(adj, p_m, p_is, p_att);
            // az = relu(att @ hh)
            sgemm_k<false,2><<<dim3(1,8,B_),256>>>(p_att, p_hh, p_az,
                N_, D_, N_, NN1, ND1, ND1, nullptr, nullptr, nullptr);
            // coeff
            coeff_k<<<2048,256>>>(p_hh, p_az, gwk, gbk, p_cf);
            // hop 1 (reuses az)
            hop1_k<<<2048,256>>>(p_hh, p_az, p_cf, zc);
            // hops 2..nhop
            for (int hp = 1; hp < nhop; hp++) {
                sgemm_k<false,3><<<dim3(1,8,B_),256>>>(p_att, zc, zn,
                    N_, D_, N_, NN1, ND1, ND1, nullptr, p_cf, p_hh);
                float* t = zc; zc = zn; zn = t;
            }
            zfin[br] = zc;
        }
        // h = z2 - z1
        sub_k<<<2048,256>>>(zfin[1], zfin[0], p_h);
    }

    pool_k<<<B_,D_>>>(p_h, valid, p_pool);
    mlp_k<<<B_,D_>>>(p_pool, fc0_w, fc0_b, fc1_w, fc1_b,
                     fc2_w, fc2_b, fc3_w, fc3_b, out);
}

// round 4
// speedup vs baseline: 2.4393x; 2.4393x over previous
#include <cuda_runtime.h>
#include <math.h>

#define B_ 16
#define N_ 1024
#define D_ 128
#define L_ 4
#define BN_ (B_*N_)
#define EMAX (1<<22)
#define NN1 ((size_t)N_*N_)
#define ND1 ((size_t)N_*D_)

__device__ __align__(128) float g_h [B_*N_*D_];
__device__ __align__(128) float g_hh[B_*N_*D_];
__device__ __align__(128) float g_hA[B_*N_*D_];
__device__ __align__(128) float g_az[B_*N_*D_];
__device__ __align__(128) float g_zA[B_*N_*D_];
__device__ __align__(128) float g_zB[B_*N_*D_];
__device__ __align__(128) float g_zC[B_*N_*D_];
__device__ __align__(128) float g_zD[B_*N_*D_];
__device__ __align__(128) float g_cf[B_*N_];
__device__ __align__(128) float g_pool[B_*D_];
__device__ __align__(128) int   g_rowptr[2][BN_ + 1];
__device__ __align__(128) int   g_col[2][EMAX];
__device__ __align__(128) int   g_mir[2][EMAX];
__device__ __align__(128) float g_ev[EMAX];
__device__ __align__(128) float g_invs[B_*N_];

// ================= dense SGEMM (embede / hh / hA) =================
template<bool TRANSB, int EPI>   // EPI: 0 none, 1 +bias
__global__ void __launch_bounds__(256, 2)
sgemm_k(const float* __restrict__ Ag, const float* __restrict__ Bg,
        float* __restrict__ Cg, int M, int Nc, int K,
        const float* __restrict__ bias)
{
    __shared__ float As[16][132];
    __shared__ float Bs[16][132];
    const int tid = threadIdx.x;
    const int tx = tid & 15, ty = tid >> 4;
    const int mbase = blockIdx.y * 128;
    const int nbase = blockIdx.x * 128;

    const int arow  = tid >> 1;
    const int akoff = (tid & 1) * 8;
    const float* aptr = Ag + (size_t)(mbase + arow) * K + akoff;

    int bkr = 0, bcoff = 0, bn = 0, bkh = 0;
    const float* bptr;
    if (!TRANSB) { bkr = tid >> 4; bcoff = (tid & 15) * 8;
                   bptr = Bg + (size_t)bkr * Nc + nbase + bcoff; }
    else         { bn = tid & 127; bkh = (tid >> 7) * 8;
                   bptr = Bg + (size_t)(nbase + bn) * K + bkh; }

    float acc[8][8];
#pragma unroll
    for (int i = 0; i < 8; i++)
#pragma unroll
        for (int j = 0; j < 8; j++) acc[i][j] = 0.f;

    float4 pa0 = *(const float4*)(aptr);
    float4 pa1 = *(const float4*)(aptr + 4);
    float4 pb0 = *(const float4*)(bptr);
    float4 pb1 = *(const float4*)(bptr + 4);

    const int nk = K >> 4;
    for (int kc = 0; kc < nk; ++kc) {
        As[akoff+0][arow]=pa0.x; As[akoff+1][arow]=pa0.y;
        As[akoff+2][arow]=pa0.z; As[akoff+3][arow]=pa0.w;
        As[akoff+4][arow]=pa1.x; As[akoff+5][arow]=pa1.y;
        As[akoff+6][arow]=pa1.z; As[akoff+7][arow]=pa1.w;
        if (!TRANSB) {
            *(float4*)&Bs[bkr][bcoff]   = pb0;
            *(float4*)&Bs[bkr][bcoff+4] = pb1;
        } else {
            Bs[bkh+0][bn]=pb0.x; Bs[bkh+1][bn]=pb0.y;
            Bs[bkh+2][bn]=pb0.z; Bs[bkh+3][bn]=pb0.w;
            Bs[bkh+4][bn]=pb1.x; Bs[bkh+5][bn]=pb1.y;
            Bs[bkh+6][bn]=pb1.z; Bs[bkh+7][bn]=pb1.w;
        }
        __syncthreads();
        if (kc + 1 < nk) {
            const float* ap = aptr + (kc + 1) * 16;
            pa0 = *(const float4*)ap; pa1 = *(const float4*)(ap + 4);
            const float* bp = TRANSB ? (bptr + (kc + 1) * 16)
                                     : (bptr + (size_t)(kc + 1) * 16 * Nc);
            pb0 = *(const float4*)bp; pb1 = *(const float4*)(bp + 4);
        }
#pragma unroll
        for (int kk = 0; kk < 16; ++kk) {
            float4 av0 = *(const float4*)&As[kk][ty*8];
            float4 av1 = *(const float4*)&As[kk][ty*8+4];
            float4 bv0 = *(const float4*)&Bs[kk][tx*8];
            float4 bv1 = *(const float4*)&Bs[kk][tx*8+4];
            float ar[8] = {av0.x,av0.y,av0.z,av0.w,av1.x,av1.y,av1.z,av1.w};
            float br[8] = {bv0.x,bv0.y,bv0.z,bv0.w,bv1.x,bv1.y,bv1.z,bv1.w};
#pragma unroll
            for (int i = 0; i < 8; i++)
#pragma unroll
                for (int j = 0; j < 8; j++)
                    acc[i][j] += ar[i] * br[j];
        }
        __syncthreads();
    }

    const int row0 = mbase + ty * 8;
    const int col0 = nbase + tx * 8;
#pragma unroll
    for (int i = 0; i < 8; i++) {
        const int row = row0 + i;
        float o[8];
#pragma unroll
        for (int j = 0; j < 8; j++) {
            float v = acc[i][j];
            if (EPI == 1) v += bias[col0 + j];
            o[j] = v;
        }
        float4* cp = (float4*)(Cg + (size_t)row * Nc + col0);
        cp[0] = make_float4(o[0], o[1], o[2], o[3]);
        cp[1] = make_float4(o[4], o[5], o[6], o[7]);
    }
}

// ================= CSR build (once per adj) =================
__global__ void deg_k(const float* __restrict__ adj, int* __restrict__ rp)
{
    const int wid = (blockIdx.x * blockDim.x + threadIdx.x) >> 5;
    const int lane = threadIdx.x & 31;
    if (wid >= BN_) return;
    const float* row = adj + (size_t)wid * N_;
    int c = 0;
#pragma unroll 4
    for (int k = 0; k < 32; k++) c += (row[lane + k * 32] > 0.f) ? 1 : 0;
    for (int o = 16; o; o >>= 1) c += __shfl_xor_sync(0xFFFFFFFFu, c, o);
    if (lane == 0) rp[wid + 1] = c;
}

__global__ void scan_k(int* __restrict__ rp)
{
    __shared__ int part[1024];
    const int t = threadIdx.x;
    int loc[16];
    int run = 0;
#pragma unroll
    for (int k = 0; k < 16; k++) { run += rp[1 + t * 16 + k]; loc[k] = run; }
    part[t] = run;
    __syncthreads();
    for (int off = 1; off < 1024; off <<= 1) {
        int v = (t >= off) ? part[t - off] : 0;
        __syncthreads();
        part[t] += v;
        __syncthreads();
    }
    const int excl = (t == 0) ? 0 : part[t - 1];
#pragma unroll
    for (int k = 0; k < 16; k++) rp[1 + t * 16 + k] = excl + loc[k];
    if (t == 0) rp[0] = 0;
}

__global__ void fill_k(const float* __restrict__ adj, const int* __restrict__ rp,
                       int* __restrict__ col)
{
    const int wid = (blockIdx.x * blockDim.x + threadIdx.x) >> 5;
    const int lane = threadIdx.x & 31;
    if (wid >= BN_) return;
    const float* row = adj + (size_t)wid * N_;
    const int c0 = lane * 32;
    int cnt = 0;
#pragma unroll 4
    for (int k = 0; k < 32; k++) cnt += (row[c0 + k] > 0.f) ? 1 : 0;
    // exclusive warp scan
    int inc = cnt;
    for (int off = 1; off < 32; off <<= 1) {
        int v = __shfl_up_sync(0xFFFFFFFFu, inc, off);
        if (lane >= off) inc += v;
    }
    int pos = rp[wid] + (inc - cnt);
    for (int k = 0; k < 32; k++)
        if (row[c0 + k] > 0.f) col[pos++] = c0 + k;
}

__global__ void mirror_k(const int* __restrict__ rp, const int* __restrict__ col,
                         int* __restrict__ mir)
{
    const int wid = (blockIdx.x * blockDim.x + threadIdx.x) >> 5;
    const int lane = threadIdx.x & 31;
    if (wid >= BN_) return;
    const int i = wid & (N_ - 1);
    const int bN = wid - i;
    const int rs = rp[wid], re = rp[wid + 1];
    for (int e = rs + lane; e < re; e += 32) {
        const int j = col[e];
        int lo = rp[bN + j], hi = rp[bN + j + 1];
        while (lo < hi) {                 // find col==i in row j (sorted)
            int mid = (lo + hi) >> 1;
            if (col[mid] < i) lo = mid + 1; else hi = mid;
        }
        mir[e] = lo;
    }
}

// ================= edge logits: ev = exp(hA_i.hh_j + hh_i.hA_j) ===========
__global__ void __launch_bounds__(128)
elog_k(const float* __restrict__ hh, const float* __restrict__ hA,
       const int* __restrict__ rp, const int* __restrict__ col,
       const int* __restrict__ mir, float* __restrict__ ev)
{
    __shared__ float shh[128], sha[128];
    const int i = blockIdx.x, b = blockIdx.y;
    const int r = b * N_ + i;
    const int t = threadIdx.x;
    shh[t] = hh[(size_t)r * D_ + t];
    sha[t] = hA[(size_t)r * D_ + t];
    __syncthreads();
    const int w = t >> 5, lane = t & 31;
    const int rs = rp[r], re = rp[r + 1];
    const float4 a1 = *(const float4*)(sha + lane * 4);
    const float4 h1 = *(const float4*)(shh + lane * 4);
    for (int e = rs + w; e < re; e += 4) {
        const int j = col[e];
        if (j < i) continue;             // symmetric: compute once
        const float* hj = hh + ((size_t)(b * N_ + j)) * D_ + lane * 4;
        const float* aj = hA + ((size_t)(b * N_ + j)) * D_ + lane * 4;
        const float4 h2 = *(const float4*)hj;
        const float4 a2 = *(const float4*)aj;
        float p = a1.x*h2.x + a1.y*h2.y + a1.z*h2.z + a1.w*h2.w
                + h1.x*a2.x + h1.y*a2.y + h1.z*a2.z + h1.w*a2.w;
        for (int o = 16; o; o >>= 1) p += __shfl_xor_sync(0xFFFFFFFFu, p, o);
        if (lane == 0) {
            const float x = __expf(p);
            ev[e] = x;
            ev[mir[e]] = x;
        }
    }
}

// ===== column softmax denominators (symmetric -> row sums), no max needed ===
__global__ void stats_k(const int* __restrict__ rp, const float* __restrict__ ev,
                        float* __restrict__ invs)
{
    const int wid = (blockIdx.x * blockDim.x + threadIdx.x) >> 5;
    const int lane = threadIdx.x & 31;
    if (wid >= BN_) return;
    const int rs = rp[wid], re = rp[wid + 1];
    float s = 0.f;
    for (int e = rs + lane; e < re; e += 32) s += ev[e];
    for (int o = 16; o; o >>= 1) s += __shfl_xor_sync(0xFFFFFFFFu, s, o);
    if (lane == 0) invs[wid] = 1.f / (s + (float)(N_ - (re - rs)));
}

// ================= SpMM: out[i] = f( sum_j att_ij * z[j] ) =================
// EPI 2: relu    EPI 3: cf*Hres + (1-cf)*relu(.)
template<int EPI>
__global__ void __launch_bounds__(256)
spmm_k(const int* __restrict__ rp, const int* __restrict__ col,
       const float* __restrict__ ev, const float* __restrict__ invs,
       const float* __restrict__ Z, float* __restrict__ out,
       const float* __restrict__ Hres, const float* __restrict__ cf)
{
    const int wid = blockIdx.x * 8 + (threadIdx.x >> 5);
    const int lane = threadIdx.x & 31;
    if (wid >= BN_) return;
    const int bN = wid & ~(N_ - 1);
    const float* zb = Z + (size_t)bN * D_;
    const float* isb = invs + bN;
    const int rs = rp[wid], re = rp[wid + 1];

    float4 acc = make_float4(0.f, 0.f, 0.f, 0.f);
    int e = rs;
    int j = 0; float a0 = 0.f;
    if (e < re) { j = col[e]; a0 = ev[e]; }
    while (e < re) {
        int jn = 0; float an = 0.f;
        if (e + 1 < re) { jn = col[e + 1]; an = ev[e + 1]; }
        const float a = a0 * isb[j];
        const float4 zv = *(const float4*)(zb + (size_t)j * D_ + lane * 4);
        acc.x += a * zv.x; acc.y += a * zv.y;
        acc.z += a * zv.z; acc.w += a * zv.w;
        j = jn; a0 = an; ++e;
    }

    float4 o;
    if (EPI == 2) {
        o.x = fmaxf(acc.x, 0.f); o.y = fmaxf(acc.y, 0.f);
        o.z = fmaxf(acc.z, 0.f); o.w = fmaxf(acc.w, 0.f);
    } else {
        const float c = cf[wid], om = 1.f - c;
        const float4 hv = *(const float4*)(Hres + (size_t)wid * D_ + lane * 4);
        o.x = c * hv.x + om * fmaxf(acc.x, 0.f);
        o.y = c * hv.y + om * fmaxf(acc.y, 0.f);
        o.z = c * hv.z + om * fmaxf(acc.z, 0.f);
        o.w = c * hv.w + om * fmaxf(acc.w, 0.f);
    }
    *(float4*)(out + (size_t)wid * D_ + lane * 4) = o;
}

// ================= small elementwise / tail kernels =================
__global__ void coeff_k(const float* __restrict__ h, const float* __restrict__ az,
                        const float* __restrict__ gw, const float* __restrict__ gb,
                        float* __restrict__ cf)
{
    const int row = (blockIdx.x * blockDim.x + threadIdx.x) >> 5;
    const int lane = threadIdx.x & 31;
    if (row >= BN_) return;
    const float* hp = h + (size_t)row * D_;
    const float* ap = az + (size_t)row * D_;
    float s = 0.f;
    for (int i = lane; i < D_; i += 32) s += hp[i]*gw[i] + ap[i]*gw[D_+i];
    for (int o = 16; o; o >>= 1) s += __shfl_xor_sync(0xFFFFFFFFu, s, o);
    if (lane == 0) cf[row] = 1.f / (1.f + __expf(-(s + gb[0])));
}

__global__ void hop1_k(const float* __restrict__ h, const float* __restrict__ az,
                       const float* __restrict__ cf, float* __restrict__ z)
{
    const size_t i = (size_t)blockIdx.x * blockDim.x + threadIdx.x;
    const int row = (int)(i >> 5);
    const float c = cf[row], om = 1.f - c;
    float4 hv = ((const float4*)h)[i];
    float4 av = ((const float4*)az)[i];
    float4 o;
    o.x = c*hv.x + om*av.x; o.y = c*hv.y + om*av.y;
    o.z = c*hv.z + om*av.z; o.w = c*hv.w + om*av.w;
    ((float4*)z)[i] = o;
}

__global__ void sub_k(const float* __restrict__ z2, const float* __restrict__ z1,
                      float* __restrict__ o)
{
    const size_t i = (size_t)blockIdx.x * blockDim.x + threadIdx.x;
    float4 a = ((const float4*)z2)[i];
    float4 b = ((const float4*)z1)[i];
    ((float4*)o)[i] = make_float4(a.x-b.x, a.y-b.y, a.z-b.z, a.w-b.w);
}

__global__ void pool_k(const float* __restrict__ h, const float* __restrict__ valid,
                       float* __restrict__ pooled)
{
    const int b = blockIdx.x, d = threadIdx.x;
    float s = 0.f, vs = 0.f;
    for (int n = 0; n < N_; n++) {
        float v = valid[b * N_ + n];
        s += h[((size_t)b * N_ + n) * D_ + d] * v;
        vs += v;
    }
    pooled[b * D_ + d] = s / vs;
}

__global__ void mlp_k(const float* __restrict__ pooled,
                      const float* __restrict__ w0, const float* __restrict__ b0,
                      const float* __restrict__ w1, const float* __restrict__ b1,
                      const float* __restrict__ w2, const float* __restrict__ b2,
                      const float* __restrict__ w3, const float* __restrict__ b3,
                      float* __restrict__ out)
{
    __shared__ float a0[128], a1[128], red[4];
    const int b = blockIdx.x, t = threadIdx.x;
    a0[t] = pooled[b * 128 + t];
    __syncthreads();
    float s = 0.f;
    for (int i = 0; i < 128; i++) s += a0[i] * w0[t*128+i];
    a1[t] = fmaxf(s + b0[t], 0.f);
    __syncthreads();
    s = 0.f;
    for (int i = 0; i < 128; i++) s += a1[i] * w1[t*128+i];
    a0[t] = fmaxf(s + b1[t], 0.f);
    __syncthreads();
    s = 0.f;
    for (int i = 0; i < 128; i++) s += a0[i] * w2[t*128+i];
    a1[t] = fmaxf(s + b2[t], 0.f);
    __syncthreads();
    float p = a1[t] * w3[t];
    for (int o = 16; o; o >>= 1) p += __shfl_xor_sync(0xFFFFFFFFu, p, o);
    if ((t & 31) == 0) red[t >> 5] = p;
    __syncthreads();
    if (t == 0) {
        float tot = red[0] + red[1] + red[2] + red[3] + b3[0];
        out[b] = 1.f / (1.f + expf(-tot));
    }
}

extern "C" void kernel_launch(void* const* d_in, const int* in_sizes, int n_in,
                              void* d_out, int out_size)
{
    const float* x       = (const float*)d_in[0];
    const float* adj1    = (const float*)d_in[1];
    const float* adj2    = (const float*)d_in[2];
    const float* valid   = (const float*)d_in[3];
    const float* embede_w= (const float*)d_in[4];
    const float* gW      = (const float*)d_in[5];
    const float* gb      = (const float*)d_in[6];
    const float* gA      = (const float*)d_in[7];
    const float* gate_w  = (const float*)d_in[8];
    const float* gate_b  = (const float*)d_in[9];
    const float* fc0_w   = (const float*)d_in[10];
    const float* fc0_b   = (const float*)d_in[11];
    const float* fc1_w   = (const float*)d_in[12];
    const float* fc1_b   = (const float*)d_in[13];
    const float* fc2_w   = (const float*)d_in[14];
    const float* fc2_b   = (const float*)d_in[15];
    const float* fc3_w   = (const float*)d_in[16];
    const float* fc3_b   = (const float*)d_in[17];
    float* out = (float*)d_out;

    float *p_h, *p_hh, *p_hA, *p_az, *p_zA, *p_zB, *p_zC, *p_zD,
          *p_cf, *p_pool, *p_ev, *p_invs;
    int *p_rp, *p_col, *p_mir;
    cudaGetSymbolAddress((void**)&p_h,  g_h);
    cudaGetSymbolAddress((void**)&p_hh, g_hh);
    cudaGetSymbolAddress((void**)&p_hA, g_hA);
    cudaGetSymbolAddress((void**)&p_az, g_az);
    cudaGetSymbolAddress((void**)&p_zA, g_zA);
    cudaGetSymbolAddress((void**)&p_zB, g_zB);
    cudaGetSymbolAddress((void**)&p_zC, g_zC);
    cudaGetSymbolAddress((void**)&p_zD, g_zD);
    cudaGetSymbolAddress((void**)&p_cf, g_cf);
    cudaGetSymbolAddress((void**)&p_pool, g_pool);
    cudaGetSymbolAddress((void**)&p_ev, g_ev);
    cudaGetSymbolAddress((void**)&p_invs, g_invs);
    cudaGetSymbolAddress((void**)&p_rp,  g_rowptr);
    cudaGetSymbolAddress((void**)&p_col, g_col);
    cudaGetSymbolAddress((void**)&p_mir, g_mir);

    const int NHOPS[4] = {1, 2, 3, 4};
    const float* adjs[2] = {adj1, adj2};
    int* rp_[2]  = {p_rp,  p_rp  + (BN_ + 1)};
    int* col_[2] = {p_col, p_col + EMAX};
    int* mir_[2] = {p_mir, p_mir + EMAX};

    // -------- CSR build (deterministic) --------
    for (int a = 0; a < 2; a++) {
        deg_k   <<<2048, 256>>>(adjs[a], rp_[a]);
        scan_k  <<<1, 1024>>>(rp_[a]);
        fill_k  <<<2048, 256>>>(adjs[a], rp_[a], col_[a]);
        mirror_k<<<2048, 256>>>(rp_[a], col_[a], mir_[a]);
    }

    // h = x @ embede_w^T
    sgemm_k<true,0><<<dim3(1,128,1),256>>>(x, embede_w, p_h,
        BN_, D_, D_, nullptr);

    for (int k = 0; k < L_; k++) {
        const float* Wk  = gW + (size_t)k * D_ * D_;
        const float* bk  = gb + (size_t)k * D_;
        const float* Ak  = gA + (size_t)k * D_ * D_;
        const float* gwk = gate_w + (size_t)k * 2 * D_;
        const float* gbk = gate_b + k;
        const int nhop = NHOPS[k];
        float* zfin[2];

        for (int br = 0; br < 2; br++) {
            int* rp  = rp_[br];
            int* col = col_[br];
            int* mir = mir_[br];
            float* zc = br ? p_zC : p_zA;
            float* zn = br ? p_zD : p_zB;

            // hh = h @ Wk^T + bk ; hA = hh @ Ak
            sgemm_k<true,1><<<dim3(1,128,1),256>>>(p_h, Wk, p_hh,
                BN_, D_, D_, bk);
            sgemm_k<false,0><<<dim3(1,128,1),256>>>(p_hh, Ak, p_hA,
                BN_, D_, D_, nullptr);
            // sparse logits (exp), softmax denominators
            elog_k <<<dim3(N_, B_), 128>>>(p_hh, p_hA, rp, col, mir, p_ev);
            stats_k<<<2048, 256>>>(rp, p_ev, p_invs);
            // az = relu(att @ hh)
            spmm_k<2><<<2048, 256>>>(rp, col, p_ev, p_invs, p_hh, p_az,
                                     nullptr, nullptr);
            // gate + hop 1
            coeff_k<<<2048, 256>>>(p_hh, p_az, gwk, gbk, p_cf);
            hop1_k<<<2048, 256>>>(p_hh, p_az, p_cf, zc);
            // hops 2..nhop
            for (int hp = 1; hp < nhop; hp++) {
                spmm_k<3><<<2048, 256>>>(rp, col, p_ev, p_invs, zc, zn,
                                         p_hh, p_cf);
                float* t = zc; zc = zn; zn = t;
            }
            zfin[br] = zc;
        }
        sub_k<<<2048, 256>>>(zfin[1], zfin[0], p_h);
    }

    pool_k<<<B_, D_>>>(p_h, valid, p_pool);
    mlp_k<<<B_, D_>>>(p_pool, fc0_w, fc0_b, fc1_w, fc1_b,
                      fc2_w, fc2_b, fc3_w, fc3_b, out);
}

// round 5
// speedup vs baseline: 2.7737x; 1.1371x over previous
#include <cuda_runtime.h>
#include <math.h>

#define B_ 16
#define N_ 1024
#define D_ 128
#define L_ 4
#define BN_ (B_*N_)
#define EMAX (1<<22)

__device__ __align__(128) float g_h [B_*N_*D_];
__device__ __align__(128) float g_hh[B_*N_*D_];
__device__ __align__(128) float g_hA[B_*N_*D_];
__device__ __align__(128) float g_zA[B_*N_*D_];
__device__ __align__(128) float g_zB[B_*N_*D_];
__device__ __align__(128) float g_zC[B_*N_*D_];
__device__ __align__(128) float g_zD[B_*N_*D_];
__device__ __align__(128) float g_cf[B_*N_];
__device__ __align__(128) float g_pool[B_*D_];
__device__ __align__(128) int   g_rowptr[2][BN_ + 1];
__device__ __align__(128) int   g_us[2][BN_];
__device__ __align__(128) int   g_col[2][EMAX];
__device__ __align__(128) int   g_mir[2][EMAX];
__device__ __align__(128) float g_ev[EMAX];
__device__ __align__(128) float g_av[EMAX];
__device__ __align__(128) float g_invs[B_*N_];

// ============ dense SGEMM: 64x128 tile, 4x8/thread ============
template<bool TRANSB, int EPI>   // EPI: 0 none, 1 +bias
__global__ void __launch_bounds__(256)
sgemm_k(const float* __restrict__ Ag, const float* __restrict__ Bg,
        float* __restrict__ Cg, int M, int Nc, int K,
        const float* __restrict__ bias)
{
    __shared__ float As[16][68];
    __shared__ float Bs[16][132];
    const int tid = threadIdx.x;
    const int tx = tid & 15, ty = tid >> 4;
    const int mbase = blockIdx.y * 64;
    const int nbase = blockIdx.x * 128;

    const int arow  = tid >> 2;          // 0..63
    const int akoff = (tid & 3) * 4;     // 0,4,8,12
    const float* aptr = Ag + (size_t)(mbase + arow) * K + akoff;

    int bkr = 0, bcoff = 0, bn = 0, bkh = 0;
    const float* bptr;
    if (!TRANSB) { bkr = tid >> 4; bcoff = (tid & 15) * 8;
                   bptr = Bg + (size_t)bkr * Nc + nbase + bcoff; }
    else         { bn = tid & 127; bkh = (tid >> 7) * 8;
                   bptr = Bg + (size_t)(nbase + bn) * K + bkh; }

    float acc[4][8];
#pragma unroll
    for (int i = 0; i < 4; i++)
#pragma unroll
        for (int j = 0; j < 8; j++) acc[i][j] = 0.f;

    float4 pa  = *(const float4*)(aptr);
    float4 pb0 = *(const float4*)(bptr);
    float4 pb1 = *(const float4*)(bptr + 4);

    const int nk = K >> 4;
    for (int kc = 0; kc < nk; ++kc) {
        As[akoff+0][arow]=pa.x; As[akoff+1][arow]=pa.y;
        As[akoff+2][arow]=pa.z; As[akoff+3][arow]=pa.w;
        if (!TRANSB) {
            *(float4*)&Bs[bkr][bcoff]   = pb0;
            *(float4*)&Bs[bkr][bcoff+4] = pb1;
        } else {
            Bs[bkh+0][bn]=pb0.x; Bs[bkh+1][bn]=pb0.y;
            Bs[bkh+2][bn]=pb0.z; Bs[bkh+3][bn]=pb0.w;
            Bs[bkh+4][bn]=pb1.x; Bs[bkh+5][bn]=pb1.y;
            Bs[bkh+6][bn]=pb1.z; Bs[bkh+7][bn]=pb1.w;
        }
        __syncthreads();
        if (kc + 1 < nk) {
            pa  = *(const float4*)(aptr + (kc + 1) * 16);
            const float* bp = TRANSB ? (bptr + (kc + 1) * 16)
                                     : (bptr + (size_t)(kc + 1) * 16 * Nc);
            pb0 = *(const float4*)bp; pb1 = *(const float4*)(bp + 4);
        }
#pragma unroll
        for (int kk = 0; kk < 16; ++kk) {
            float4 av0 = *(const float4*)&As[kk][ty*4];
            float4 bv0 = *(const float4*)&Bs[kk][tx*8];
            float4 bv1 = *(const float4*)&Bs[kk][tx*8+4];
            float ar[4] = {av0.x,av0.y,av0.z,av0.w};
            float br[8] = {bv0.x,bv0.y,bv0.z,bv0.w,bv1.x,bv1.y,bv1.z,bv1.w};
#pragma unroll
            for (int i = 0; i < 4; i++)
#pragma unroll
                for (int j = 0; j < 8; j++)
                    acc[i][j] += ar[i] * br[j];
        }
        __syncthreads();
    }

    const int row0 = mbase + ty * 4;
    const int col0 = nbase + tx * 8;
#pragma unroll
    for (int i = 0; i < 4; i++) {
        float o[8];
#pragma unroll
        for (int j = 0; j < 8; j++) {
            float v = acc[i][j];
            if (EPI == 1) v += bias[col0 + j];
            o[j] = v;
        }
        float4* cp = (float4*)(Cg + (size_t)(row0 + i) * Nc + col0);
        cp[0] = make_float4(o[0], o[1], o[2], o[3]);
        cp[1] = make_float4(o[4], o[5], o[6], o[7]);
    }
}

// ============ CSR build ============
__global__ void deg_k(const float* __restrict__ adj, int* __restrict__ rp)
{
    const int wid = (blockIdx.x * blockDim.x + threadIdx.x) >> 5;
    const int lane = threadIdx.x & 31;
    if (wid >= BN_) return;
    const float* row = adj + (size_t)wid * N_;
    int c = 0;
#pragma unroll 4
    for (int k = 0; k < 32; k++) c += (row[lane + k * 32] > 0.f) ? 1 : 0;
    for (int o = 16; o; o >>= 1) c += __shfl_xor_sync(0xFFFFFFFFu, c, o);
    if (lane == 0) rp[wid + 1] = c;
}

__global__ void scan_k(int* __restrict__ rp)
{
    __shared__ int part[1024];
    const int t = threadIdx.x;
    int loc[16];
    int run = 0;
#pragma unroll
    for (int k = 0; k < 16; k++) { run += rp[1 + t * 16 + k]; loc[k] = run; }
    part[t] = run;
    __syncthreads();
    for (int off = 1; off < 1024; off <<= 1) {
        int v = (t >= off) ? part[t - off] : 0;
        __syncthreads();
        part[t] += v;
        __syncthreads();
    }
    const int excl = (t == 0) ? 0 : part[t - 1];
#pragma unroll
    for (int k = 0; k < 16; k++) rp[1 + t * 16 + k] = excl + loc[k];
    if (t == 0) rp[0] = 0;
}

__global__ void fill_k(const float* __restrict__ adj, const int* __restrict__ rp,
                       int* __restrict__ col)
{
    const int wid = (blockIdx.x * blockDim.x + threadIdx.x) >> 5;
    const int lane = threadIdx.x & 31;
    if (wid >= BN_) return;
    const float* row = adj + (size_t)wid * N_;
    const int c0 = lane * 32;
    int cnt = 0;
#pragma unroll 4
    for (int k = 0; k < 32; k++) cnt += (row[c0 + k] > 0.f) ? 1 : 0;
    int inc = cnt;
    for (int off = 1; off < 32; off <<= 1) {
        int v = __shfl_up_sync(0xFFFFFFFFu, inc, off);
        if (lane >= off) inc += v;
    }
    int pos = rp[wid] + (inc - cnt);
    for (int k = 0; k < 32; k++)
        if (row[c0 + k] > 0.f) col[pos++] = c0 + k;
}

// mirror index + upper-start (position of diagonal, self-loops guaranteed)
__global__ void mirror_k(const int* __restrict__ rp, const int* __restrict__ col,
                         int* __restrict__ mir, int* __restrict__ us)
{
    const int wid = (blockIdx.x * blockDim.x + threadIdx.x) >> 5;
    const int lane = threadIdx.x & 31;
    if (wid >= BN_) return;
    const int i = wid & (N_ - 1);
    const int bN = wid - i;
    const int rs = rp[wid], re = rp[wid + 1];
    for (int e = rs + lane; e < re; e += 32) {
        const int j = col[e];
        if (j == i) us[wid] = e;
        int lo = rp[bN + j], hi = rp[bN + j + 1];
        while (lo < hi) {
            int mid = (lo + hi) >> 1;
            if (col[mid] < i) lo = mid + 1; else hi = mid;
        }
        mir[e] = lo;
    }
}

// ============ edge logits (upper only, mirrored write) ============
__global__ void __launch_bounds__(128)
elog_k(const float* __restrict__ hh, const float* __restrict__ hA,
       const int* __restrict__ rp, const int* __restrict__ col,
       const int* __restrict__ mir, const int* __restrict__ us,
       float* __restrict__ ev)
{
    __shared__ float shh[128], sha[128];
    const int i = blockIdx.x, b = blockIdx.y;
    const int r = b * N_ + i;
    const int t = threadIdx.x;
    shh[t] = hh[(size_t)r * D_ + t];
    sha[t] = hA[(size_t)r * D_ + t];
    __syncthreads();
    const int w = t >> 5, lane = t & 31;
    const int rs = us[r], re = rp[r + 1];
    const float4 a1 = *(const float4*)(sha + lane * 4);
    const float4 h1 = *(const float4*)(shh + lane * 4);
    for (int e = rs + w; e < re; e += 4) {
        const int j = col[e];
        const float4 h2 = *(const float4*)(hh + ((size_t)(b * N_ + j)) * D_ + lane * 4);
        const float4 a2 = *(const float4*)(hA + ((size_t)(b * N_ + j)) * D_ + lane * 4);
        float p = a1.x*h2.x + a1.y*h2.y + a1.z*h2.z + a1.w*h2.w
                + h1.x*a2.x + h1.y*a2.y + h1.z*a2.z + h1.w*a2.w;
        for (int o = 16; o; o >>= 1) p += __shfl_xor_sync(0xFFFFFFFFu, p, o);
        if (lane == 0) {
            const float x = __expf(p);
            ev[e] = x;
            ev[mir[e]] = x;
        }
    }
}

// ===== softmax denominators (symmetric -> row sums; zeros in denominator) ===
__global__ void stats_k(const int* __restrict__ rp, const float* __restrict__ ev,
                        float* __restrict__ invs)
{
    const int wid = (blockIdx.x * blockDim.x + threadIdx.x) >> 5;
    const int lane = threadIdx.x & 31;
    if (wid >= BN_) return;
    const int rs = rp[wid], re = rp[wid + 1];
    float s = 0.f;
    for (int e = rs + lane; e < re; e += 32) s += ev[e];
    for (int o = 16; o; o >>= 1) s += __shfl_xor_sync(0xFFFFFFFFu, s, o);
    if (lane == 0) invs[wid] = 1.f / (s + (float)(N_ - (re - rs)));
}

// ===== fold column normalizer into edge values: av = ev * invs[col] =====
__global__ void fold_k(const int* __restrict__ rp, const int* __restrict__ col,
                       const float* __restrict__ ev, const float* __restrict__ invs,
                       float* __restrict__ av)
{
    const int wid = (blockIdx.x * blockDim.x + threadIdx.x) >> 5;
    const int lane = threadIdx.x & 31;
    if (wid >= BN_) return;
    const int bN = wid & ~(N_ - 1);
    const int rs = rp[wid], re = rp[wid + 1];
    for (int e = rs + lane; e < re; e += 32)
        av[e] = ev[e] * invs[bN + col[e]];
}

// ============ SpMM (warp/row, 4-edge unrolled gather) ============
// FIRST: az=relu(att@hh); cf=sigmoid([hh,az]@gw+gb); out=cf*hh+(1-cf)*az
// else : out=cf*hh+(1-cf)*relu(att@Z)
// zsub!=null: out -= zsub  (branch2 - branch1 fused)
template<bool FIRST>
__global__ void __launch_bounds__(256)
spmm_k(const int* __restrict__ rp, const int* __restrict__ col,
       const float* __restrict__ av, const float* __restrict__ Z,
       float* __restrict__ out, const float* __restrict__ hh,
       float* __restrict__ cf, const float* __restrict__ gw,
       const float* __restrict__ gb, const float* __restrict__ zsub)
{
    const int wid = blockIdx.x * 8 + (threadIdx.x >> 5);
    const int lane = threadIdx.x & 31;
    if (wid >= BN_) return;
    const int bN = wid & ~(N_ - 1);
    const float* zb = Z + (size_t)bN * D_;
    const int rs = rp[wid], re = rp[wid + 1];
    const int off = lane * 4;

    float4 acc = make_float4(0.f, 0.f, 0.f, 0.f);
    int e = rs;
    for (; e + 4 <= re; e += 4) {
        const int   j0 = col[e],   j1 = col[e+1], j2 = col[e+2], j3 = col[e+3];
        const float a0 = av[e],    a1 = av[e+1],  a2 = av[e+2],  a3 = av[e+3];
        const float4 z0 = *(const float4*)(zb + (size_t)j0 * D_ + off);
        const float4 z1 = *(const float4*)(zb + (size_t)j1 * D_ + off);
        const float4 z2 = *(const float4*)(zb + (size_t)j2 * D_ + off);
        const float4 z3 = *(const float4*)(zb + (size_t)j3 * D_ + off);
        acc.x += a0*z0.x + a1*z1.x + a2*z2.x + a3*z3.x;
        acc.y += a0*z0.y + a1*z1.y + a2*z2.y + a3*z3.y;
        acc.z += a0*z0.z + a1*z1.z + a2*z2.z + a3*z3.z;
        acc.w += a0*z0.w + a1*z1.w + a2*z2.w + a3*z3.w;
    }
    for (; e < re; ++e) {
        const int j = col[e];
        const float a = av[e];
        const float4 zv = *(const float4*)(zb + (size_t)j * D_ + off);
        acc.x += a*zv.x; acc.y += a*zv.y; acc.z += a*zv.z; acc.w += a*zv.w;
    }

    acc.x = fmaxf(acc.x, 0.f); acc.y = fmaxf(acc.y, 0.f);
    acc.z = fmaxf(acc.z, 0.f); acc.w = fmaxf(acc.w, 0.f);
    const float4 hv = *(const float4*)(hh + (size_t)wid * D_ + off);

    float c;
    if (FIRST) {
        const float4 g1 = *(const float4*)(gw + off);
        const float4 g2 = *(const float4*)(gw + D_ + off);
        float s = hv.x*g1.x + hv.y*g1.y + hv.z*g1.z + hv.w*g1.w
                + acc.x*g2.x + acc.y*g2.y + acc.z*g2.z + acc.w*g2.w;
        for (int o = 16; o; o >>= 1) s += __shfl_xor_sync(0xFFFFFFFFu, s, o);
        c = 1.f / (1.f + __expf(-(s + gb[0])));
        if (lane == 0) cf[wid] = c;
    } else {
        c = cf[wid];
    }
    const float om = 1.f - c;
    float4 o;
    o.x = c*hv.x + om*acc.x; o.y = c*hv.y + om*acc.y;
    o.z = c*hv.z + om*acc.z; o.w = c*hv.w + om*acc.w;
    if (zsub) {
        const float4 zs = *(const float4*)(zsub + (size_t)wid * D_ + off);
        o.x -= zs.x; o.y -= zs.y; o.z -= zs.z; o.w -= zs.w;
    }
    *(float4*)(out + (size_t)wid * D_ + off) = o;
}

// ============ tail ============
__global__ void pool_k(const float* __restrict__ h, const float* __restrict__ valid,
                       float* __restrict__ pooled)
{
    const int b = blockIdx.x, d = threadIdx.x;
    float s = 0.f, vs = 0.f;
#pragma unroll 8
    for (int n = 0; n < N_; n++) {
        float v = valid[b * N_ + n];
        s += h[((size_t)b * N_ + n) * D_ + d] * v;
        vs += v;
    }
    pooled[b * D_ + d] = s / vs;
}

__global__ void mlp_k(const float* __restrict__ pooled,
                      const float* __restrict__ w0, const float* __restrict__ b0,
                      const float* __restrict__ w1, const float* __restrict__ b1,
                      const float* __restrict__ w2, const float* __restrict__ b2,
                      const float* __restrict__ w3, const float* __restrict__ b3,
                      float* __restrict__ out)
{
    __shared__ float a0[128], a1[128], red[4];
    const int b = blockIdx.x, t = threadIdx.x;
    a0[t] = pooled[b * 128 + t];
    __syncthreads();
    float s = 0.f;
    for (int i = 0; i < 128; i++) s += a0[i] * w0[t*128+i];
    a1[t] = fmaxf(s + b0[t], 0.f);
    __syncthreads();
    s = 0.f;
    for (int i = 0; i < 128; i++) s += a1[i] * w1[t*128+i];
    a0[t] = fmaxf(s + b1[t], 0.f);
    __syncthreads();
    s = 0.f;
    for (int i = 0; i < 128; i++) s += a0[i] * w2[t*128+i];
    a1[t] = fmaxf(s + b2[t], 0.f);
    __syncthreads();
    float p = a1[t] * w3[t];
    for (int o = 16; o; o >>= 1) p += __shfl_xor_sync(0xFFFFFFFFu, p, o);
    if ((t & 31) == 0) red[t >> 5] = p;
    __syncthreads();
    if (t == 0) {
        float tot = red[0] + red[1] + red[2] + red[3] + b3[0];
        out[b] = 1.f / (1.f + expf(-tot));
    }
}

extern "C" void kernel_launch(void* const* d_in, const int* in_sizes, int n_in,
                              void* d_out, int out_size)
{
    const float* x       = (const float*)d_in[0];
    const float* adj1    = (const float*)d_in[1];
    const float* adj2    = (const float*)d_in[2];
    const float* valid   = (const float*)d_in[3];
    const float* embede_w= (const float*)d_in[4];
    const float* gW      = (const float*)d_in[5];
    const float* gb      = (const float*)d_in[6];
    const float* gA      = (const float*)d_in[7];
    const float* gate_w  = (const float*)d_in[8];
    const float* gate_b  = (const float*)d_in[9];
    const float* fc0_w   = (const float*)d_in[10];
    const float* fc0_b   = (const float*)d_in[11];
    const float* fc1_w   = (const float*)d_in[12];
    const float* fc1_b   = (const float*)d_in[13];
    const float* fc2_w   = (const float*)d_in[14];
    const float* fc2_b   = (const float*)d_in[15];
    const float* fc3_w   = (const float*)d_in[16];
    const float* fc3_b   = (const float*)d_in[17];
    float* out = (float*)d_out;

    float *p_h, *p_hh, *p_hA, *p_zA, *p_zB, *p_zC, *p_zD,
          *p_cf, *p_pool, *p_ev, *p_av, *p_invs;
    int *p_rp, *p_col, *p_mir, *p_us;
    cudaGetSymbolAddress((void**)&p_h,  g_h);
    cudaGetSymbolAddress((void**)&p_hh, g_hh);
    cudaGetSymbolAddress((void**)&p_hA, g_hA);
    cudaGetSymbolAddress((void**)&p_zA, g_zA);
    cudaGetSymbolAddress((void**)&p_zB, g_zB);
    cudaGetSymbolAddress((void**)&p_zC, g_zC);
    cudaGetSymbolAddress((void**)&p_zD, g_zD);
    cudaGetSymbolAddress((void**)&p_cf, g_cf);
    cudaGetSymbolAddress((void**)&p_pool, g_pool);
    cudaGetSymbolAddress((void**)&p_ev, g_ev);
    cudaGetSymbolAddress((void**)&p_av, g_av);
    cudaGetSymbolAddress((void**)&p_invs, g_invs);
    cudaGetSymbolAddress((void**)&p_rp,  g_rowptr);
    cudaGetSymbolAddress((void**)&p_col, g_col);
    cudaGetSymbolAddress((void**)&p_mir, g_mir);
    cudaGetSymbolAddress((void**)&p_us,  g_us);

    const int NHOPS[4] = {1, 2, 3, 4};
    const float* adjs[2] = {adj1, adj2};
    int* rp_[2]  = {p_rp,  p_rp  + (BN_ + 1)};
    int* col_[2] = {p_col, p_col + EMAX};
    int* mir_[2] = {p_mir, p_mir + EMAX};
    int* us_[2]  = {p_us,  p_us  + BN_};

    for (int a = 0; a < 2; a++) {
        deg_k   <<<2048, 256>>>(adjs[a], rp_[a]);
        scan_k  <<<1, 1024>>>(rp_[a]);
        fill_k  <<<2048, 256>>>(adjs[a], rp_[a], col_[a]);
        mirror_k<<<2048, 256>>>(rp_[a], col_[a], mir_[a], us_[a]);
    }

    // h = x @ embede_w^T
    sgemm_k<true,0><<<dim3(1,256,1),256>>>(x, embede_w, p_h,
        BN_, D_, D_, nullptr);

    float* zfin0 = nullptr;
    for (int k = 0; k < L_; k++) {
        const float* Wk  = gW + (size_t)k * D_ * D_;
        const float* bk  = gb + (size_t)k * D_;
        const float* Ak  = gA + (size_t)k * D_ * D_;
        const float* gwk = gate_w + (size_t)k * 2 * D_;
        const float* gbk = gate_b + k;
        const int nhop = NHOPS[k];

        for (int br = 0; br < 2; br++) {
            int* rp  = rp_[br];
            int* col = col_[br];

            sgemm_k<true,1><<<dim3(1,256,1),256>>>(p_h, Wk, p_hh,
                BN_, D_, D_, bk);
            sgemm_k<false,0><<<dim3(1,256,1),256>>>(p_hh, Ak, p_hA,
                BN_, D_, D_, nullptr);
            elog_k <<<dim3(N_, B_), 128>>>(p_hh, p_hA, rp, col,
                                           mir_[br], us_[br], p_ev);
            stats_k<<<2048, 256>>>(rp, p_ev, p_invs);
            fold_k <<<2048, 256>>>(rp, col, p_ev, p_invs, p_av);

            float* zc = br ? p_zC : p_zA;
            float* zn = br ? p_zD : p_zB;
            const bool lastBr = (br == 1);
            const float* zsub1 = (lastBr && nhop == 1) ? zfin0 : nullptr;
            float* out1 = (lastBr && nhop == 1) ? p_h : zc;

            spmm_k<true><<<2048, 256>>>(rp, col, p_av, p_hh, out1,
                                        p_hh, p_cf, gwk, gbk, zsub1);
            zc = out1;
            for (int hp = 1; hp < nhop; hp++) {
                const bool last = (hp == nhop - 1);
                const float* zs = (lastBr && last) ? zfin0 : nullptr;
                float* outp = (lastBr && last) ? p_h : zn;
                spmm_k<false><<<2048, 256>>>(rp, col, p_av, zc, outp,
                                             p_hh, p_cf, nullptr, nullptr, zs);
                zn = zc; zc = outp;
            }
            if (br == 0) zfin0 = zc;
        }
    }

    pool_k<<<B_, D_>>>(p_h, valid, p_pool);
    mlp_k<<<B_, D_>>>(p_pool, fc0_w, fc0_b, fc1_w, fc1_b,
                      fc2_w, fc2_b, fc3_w, fc3_b, out);
}

// round 7
// speedup vs baseline: 3.3707x; 1.2152x over previous
#include <cuda_runtime.h>
#include <cuda_bf16.h>
#include <math.h>

#define B_ 16
#define N_ 1024
#define D_ 128
#define L_ 4
#define BN_ (B_*N_)
#define EMAX (1<<22)

typedef __nv_bfloat16 bf16;
typedef __nv_bfloat162 bf162;

__device__ __align__(128) float g_h [BN_*D_];
__device__ __align__(128) float g_hh[BN_*D_];
__device__ __align__(128) float g_hA[BN_*D_];
__device__ __align__(128) bf16  g_hhb[BN_*D_];
__device__ __align__(128) bf16  g_zb[4][BN_*D_];
__device__ __align__(128) float g_zA[BN_*D_];
__device__ __align__(128) float g_zC[BN_*D_];
__device__ __align__(128) float g_cf[2*BN_];
__device__ __align__(128) float g_pool[B_*D_];
__device__ __align__(128) int   g_rowptr[2][BN_ + 1];
__device__ __align__(128) int   g_us[2][BN_];
__device__ __align__(128) int   g_col[2][EMAX];
__device__ __align__(128) int   g_mir[2][EMAX];
__device__ __align__(128) float g_ev[2][EMAX];
__device__ __align__(128) float g_av[2][EMAX];
__device__ __align__(128) float g_invs[2*BN_];

// ---------- bf16 helpers ----------
__device__ __forceinline__ float4 ldz4(const bf16* p) {
    uint2 raw = *(const uint2*)p;
    bf162 lo = *reinterpret_cast<bf162*>(&raw.x);
    bf162 hi = *reinterpret_cast<bf162*>(&raw.y);
    float2 f0 = __bfloat1622float2(lo);
    float2 f1 = __bfloat1622float2(hi);
    return make_float4(f0.x, f0.y, f1.x, f1.y);
}
__device__ __forceinline__ void stz4(bf16* p, float4 v) {
    bf162 a = __floats2bfloat162_rn(v.x, v.y);
    bf162 b = __floats2bfloat162_rn(v.z, v.w);
    uint2 r;
    r.x = *reinterpret_cast<unsigned*>(&a);
    r.y = *reinterpret_cast<unsigned*>(&b);
    *(uint2*)p = r;
}

// ============ dense SGEMM: 64x128 tile, 4x8/thread ============
template<bool TRANSB, bool BIAS, bool WB16>
__global__ void __launch_bounds__(256)
sgemm_k(const float* __restrict__ Ag, const float* __restrict__ Bg,
        float* __restrict__ Cg, bf16* __restrict__ Cb,
        int M, int Nc, int K, const float* __restrict__ bias)
{
    __shared__ float As[16][68];
    __shared__ float Bs[16][132];
    const int tid = threadIdx.x;
    const int tx = tid & 15, ty = tid >> 4;
    const int mbase = blockIdx.y * 64;
    const int nbase = blockIdx.x * 128;

    const int arow  = tid >> 2;
    const int akoff = (tid & 3) * 4;
    const float* aptr = Ag + (size_t)(mbase + arow) * K + akoff;

    int bkr = 0, bcoff = 0, bn = 0, bkh = 0;
    const float* bptr;
    if (!TRANSB) { bkr = tid >> 4; bcoff = (tid & 15) * 8;
                   bptr = Bg + (size_t)bkr * Nc + nbase + bcoff; }
    else         { bn = tid & 127; bkh = (tid >> 7) * 8;
                   bptr = Bg + (size_t)(nbase + bn) * K + bkh; }

    float acc[4][8];
#pragma unroll
    for (int i = 0; i < 4; i++)
#pragma unroll
        for (int j = 0; j < 8; j++) acc[i][j] = 0.f;

    float4 pa  = *(const float4*)(aptr);
    float4 pb0 = *(const float4*)(bptr);
    float4 pb1 = *(const float4*)(bptr + 4);

    const int nk = K >> 4;
    for (int kc = 0; kc < nk; ++kc) {
        As[akoff+0][arow]=pa.x; As[akoff+1][arow]=pa.y;
        As[akoff+2][arow]=pa.z; As[akoff+3][arow]=pa.w;
        if (!TRANSB) {
            *(float4*)&Bs[bkr][bcoff]   = pb0;
            *(float4*)&Bs[bkr][bcoff+4] = pb1;
        } else {
            Bs[bkh+0][bn]=pb0.x; Bs[bkh+1][bn]=pb0.y;
            Bs[bkh+2][bn]=pb0.z; Bs[bkh+3][bn]=pb0.w;
            Bs[bkh+4][bn]=pb1.x; Bs[bkh+5][bn]=pb1.y;
            Bs[bkh+6][bn]=pb1.z; Bs[bkh+7][bn]=pb1.w;
        }
        __syncthreads();
        if (kc + 1 < nk) {
            pa  = *(const float4*)(aptr + (kc + 1) * 16);
            const float* bp = TRANSB ? (bptr + (kc + 1) * 16)
                                     : (bptr + (size_t)(kc + 1) * 16 * Nc);
            pb0 = *(const float4*)bp; pb1 = *(const float4*)(bp + 4);
        }
#pragma unroll
        for (int kk = 0; kk < 16; ++kk) {
            float4 av0 = *(const float4*)&As[kk][ty*4];
            float4 bv0 = *(const float4*)&Bs[kk][tx*8];
            float4 bv1 = *(const float4*)&Bs[kk][tx*8+4];
            float ar[4] = {av0.x,av0.y,av0.z,av0.w};
            float br[8] = {bv0.x,bv0.y,bv0.z,bv0.w,bv1.x,bv1.y,bv1.z,bv1.w};
#pragma unroll
            for (int i = 0; i < 4; i++)
#pragma unroll
                for (int j = 0; j < 8; j++)
                    acc[i][j] += ar[i] * br[j];
        }
        __syncthreads();
    }

    const int row0 = mbase + ty * 4;
    const int col0 = nbase + tx * 8;
#pragma unroll
    for (int i = 0; i < 4; i++) {
        float o[8];
#pragma unroll
        for (int j = 0; j < 8; j++) {
            float v = acc[i][j];
            if (BIAS) v += bias[col0 + j];
            o[j] = v;
        }
        float4* cp = (float4*)(Cg + (size_t)(row0 + i) * Nc + col0);
        cp[0] = make_float4(o[0], o[1], o[2], o[3]);
        cp[1] = make_float4(o[4], o[5], o[6], o[7]);
        if (WB16) {
            bf16* bp16 = Cb + (size_t)(row0 + i) * Nc + col0;
            stz4(bp16,     make_float4(o[0], o[1], o[2], o[3]));
            stz4(bp16 + 4, make_float4(o[4], o[5], o[6], o[7]));
        }
    }
}

// ============ CSR build ============
__global__ void deg_k(const float* __restrict__ adj, int* __restrict__ rp)
{
    const int wid = (blockIdx.x * blockDim.x + threadIdx.x) >> 5;
    const int lane = threadIdx.x & 31;
    if (wid >= BN_) return;
    const float* row = adj + (size_t)wid * N_;
    int c = 0;
#pragma unroll 4
    for (int k = 0; k < 32; k++) c += (row[lane + k * 32] > 0.f) ? 1 : 0;
    for (int o = 16; o; o >>= 1) c += __shfl_xor_sync(0xFFFFFFFFu, c, o);
    if (lane == 0) rp[wid + 1] = c;
}

__global__ void scan_k(int* __restrict__ rp)
{
    __shared__ int part[1024];
    const int t = threadIdx.x;
    int loc[16];
    int run = 0;
#pragma unroll
    for (int k = 0; k < 16; k++) { run += rp[1 + t * 16 + k]; loc[k] = run; }
    part[t] = run;
    __syncthreads();
    for (int off = 1; off < 1024; off <<= 1) {
        int v = (t >= off) ? part[t - off] : 0;
        __syncthreads();
        part[t] += v;
        __syncthreads();
    }
    const int excl = (t == 0) ? 0 : part[t - 1];
#pragma unroll
    for (int k = 0; k < 16; k++) rp[1 + t * 16 + k] = excl + loc[k];
    if (t == 0) rp[0] = 0;
}

__global__ void fill_k(const float* __restrict__ adj, const int* __restrict__ rp,
                       int* __restrict__ col)
{
    const int wid = (blockIdx.x * blockDim.x + threadIdx.x) >> 5;
    const int lane = threadIdx.x & 31;
    if (wid >= BN_) return;
    const float* row = adj + (size_t)wid * N_;
    const int c0 = lane * 32;
    int cnt = 0;
#pragma unroll 4
    for (int k = 0; k < 32; k++) cnt += (row[c0 + k] > 0.f) ? 1 : 0;
    int inc = cnt;
    for (int off = 1; off < 32; off <<= 1) {
        int v = __shfl_up_sync(0xFFFFFFFFu, inc, off);
        if (lane >= off) inc += v;
    }
    int pos = rp[wid] + (inc - cnt);
    for (int k = 0; k < 32; k++)
        if (row[c0 + k] > 0.f) col[pos++] = c0 + k;
}

__global__ void mirror_k(const int* __restrict__ rp, const int* __restrict__ col,
                         int* __restrict__ mir, int* __restrict__ us)
{
    const int wid = (blockIdx.x * blockDim.x + threadIdx.x) >> 5;
    const int lane = threadIdx.x & 31;
    if (wid >= BN_) return;
    const int i = wid & (N_ - 1);
    const int bN = wid - i;
    const int rs = rp[wid], re = rp[wid + 1];
    for (int e = rs + lane; e < re; e += 32) {
        const int j = col[e];
        if (j == i) us[wid] = e;
        int lo = rp[bN + j], hi = rp[bN + j + 1];
        while (lo < hi) {
            int mid = (lo + hi) >> 1;
            if (col[mid] < i) lo = mid + 1; else hi = mid;
        }
        mir[e] = lo;
    }
}

// ============ edge logits (upper only, mirrored write), both branches ======
__global__ void __launch_bounds__(128)
elog2_k(const float* __restrict__ hh, const float* __restrict__ hA,
        const int* __restrict__ rp0, const int* __restrict__ col0,
        const int* __restrict__ mir0, const int* __restrict__ us0,
        float* __restrict__ ev0,
        const int* __restrict__ rp1, const int* __restrict__ col1,
        const int* __restrict__ mir1, const int* __restrict__ us1,
        float* __restrict__ ev1)
{
    const int br = blockIdx.z;
    const int* rp  = br ? rp1  : rp0;
    const int* col = br ? col1 : col0;
    const int* mir = br ? mir1 : mir0;
    const int* us  = br ? us1  : us0;
    float*     ev  = br ? ev1  : ev0;

    __shared__ float shh[128], sha[128];
    const int i = blockIdx.x, b = blockIdx.y;
    const int r = b * N_ + i;
    const int t = threadIdx.x;
    shh[t] = hh[(size_t)r * D_ + t];
    sha[t] = hA[(size_t)r * D_ + t];
    __syncthreads();
    const int w = t >> 5, lane = t & 31;
    const int rs = us[r], re = rp[r + 1];
    const float4 a1 = *(const float4*)(sha + lane * 4);
    const float4 h1 = *(const float4*)(shh + lane * 4);
    for (int e = rs + w; e < re; e += 4) {
        const int j = col[e];
        const float4 h2 = *(const float4*)(hh + ((size_t)(b * N_ + j)) * D_ + lane * 4);
        const float4 a2 = *(const float4*)(hA + ((size_t)(b * N_ + j)) * D_ + lane * 4);
        float p = a1.x*h2.x + a1.y*h2.y + a1.z*h2.z + a1.w*h2.w
                + h1.x*a2.x + h1.y*a2.y + h1.z*a2.z + h1.w*a2.w;
        for (int o = 16; o; o >>= 1) p += __shfl_xor_sync(0xFFFFFFFFu, p, o);
        if (lane == 0) {
            const float x = __expf(p);
            ev[e] = x;
            ev[mir[e]] = x;
        }
    }
}

// ===== softmax denominators, both branches =====
__global__ void stats2_k(const int* __restrict__ rp0, const float* __restrict__ ev0,
                         const int* __restrict__ rp1, const float* __restrict__ ev1,
                         float* __restrict__ invs)
{
    const int u = blockIdx.x * 8 + (threadIdx.x >> 5);
    const int lane = threadIdx.x & 31;
    if (u >= 2 * BN_) return;
    const bool s1 = (u >= BN_);
    const int r = s1 ? u - BN_ : u;
    const int* rp = s1 ? rp1 : rp0;
    const float* ev = s1 ? ev1 : ev0;
    const int rs = rp[r], re = rp[r + 1];
    float s = 0.f;
    for (int e = rs + lane; e < re; e += 32) s += ev[e];
    for (int o = 16; o; o >>= 1) s += __shfl_xor_sync(0xFFFFFFFFu, s, o);
    if (lane == 0) invs[u] = 1.f / (s + (float)(N_ - (re - rs)));
}

// ===== fold column normalizer, both branches =====
__global__ void fold2_k(const int* __restrict__ rp0, const int* __restrict__ col0,
                        const float* __restrict__ ev0, float* __restrict__ av0,
                        const int* __restrict__ rp1, const int* __restrict__ col1,
                        const float* __restrict__ ev1, float* __restrict__ av1,
                        const float* __restrict__ invs)
{
    const int u = blockIdx.x * 8 + (threadIdx.x >> 5);
    const int lane = threadIdx.x & 31;
    if (u >= 2 * BN_) return;
    const bool s1 = (u >= BN_);
    const int r = s1 ? u - BN_ : u;
    const int* rp  = s1 ? rp1  : rp0;
    const int* col = s1 ? col1 : col0;
    const float* ev = s1 ? ev1 : ev0;
    float* av = s1 ? av1 : av0;
    const int ibase = (s1 ? BN_ : 0) + (r & ~(N_ - 1));
    const int rs = rp[r], re = rp[r + 1];
    for (int e = rs + lane; e < re; e += 32)
        av[e] = ev[e] * invs[ibase + col[e]];
}

// ============ SpMM, bf16 gather, dual-branch ============
// rows u in [0,nrows): set0 if u<BN_, else set1 (u-BN_).
// FIRST: az=relu(att@Z); cf=sigmoid([hh,az]@gw+gb); o=cf*hh+(1-cf)*az
// else : o=cf*hh+(1-cf)*relu(att@Z)
// outF*: fp32 output (nullable). outB*: bf16 output (nullable).
// zsub0: subtract (set0 rows only; used in nhop==1 branch-1 launch).
template<bool FIRST>
__global__ void __launch_bounds__(256)
spmm2_k(const int* __restrict__ rp0, const int* __restrict__ col0,
        const float* __restrict__ av0, const bf16* __restrict__ zs0,
        const int* __restrict__ rp1, const int* __restrict__ col1,
        const float* __restrict__ av1, const bf16* __restrict__ zs1,
        float* __restrict__ outF0, float* __restrict__ outF1,
        bf16* __restrict__ outB0, bf16* __restrict__ outB1,
        const float* __restrict__ hh, float* __restrict__ cf,
        const float* __restrict__ gw, const float* __restrict__ gb,
        const float* __restrict__ zsub0, int nrows)
{
    const int u = blockIdx.x * 8 + (threadIdx.x >> 5);
    const int lane = threadIdx.x & 31;
    if (u >= nrows) return;
    const bool s1 = (u >= BN_);
    const int r = s1 ? u - BN_ : u;
    const int* rp  = s1 ? rp1  : rp0;
    const int* col = s1 ? col1 : col0;
    const float* av = s1 ? av1 : av0;
    const bf16* zb = (s1 ? zs1 : zs0) + (size_t)(r & ~(N_ - 1)) * D_;
    const int rs = rp[r], re = rp[r + 1];
    const int off = lane * 4;

    float4 acc = make_float4(0.f, 0.f, 0.f, 0.f);
    int e = rs;
    for (; e + 4 <= re; e += 4) {
        const int   j0 = col[e],   j1 = col[e+1], j2 = col[e+2], j3 = col[e+3];
        const float a0 = av[e],    a1 = av[e+1],  a2 = av[e+2],  a3 = av[e+3];
        const float4 z0 = ldz4(zb + (size_t)j0 * D_ + off);
        const float4 z1 = ldz4(zb + (size_t)j1 * D_ + off);
        const float4 z2 = ldz4(zb + (size_t)j2 * D_ + off);
        const float4 z3 = ldz4(zb + (size_t)j3 * D_ + off);
        acc.x += a0*z0.x + a1*z1.x + a2*z2.x + a3*z3.x;
        acc.y += a0*z0.y + a1*z1.y + a2*z2.y + a3*z3.y;
        acc.z += a0*z0.z + a1*z1.z + a2*z2.z + a3*z3.z;
        acc.w += a0*z0.w + a1*z1.w + a2*z2.w + a3*z3.w;
    }
    for (; e < re; ++e) {
        const int j = col[e];
        const float a = av[e];
        const float4 zv = ldz4(zb + (size_t)j * D_ + off);
        acc.x += a*zv.x; acc.y += a*zv.y; acc.z += a*zv.z; acc.w += a*zv.w;
    }

    acc.x = fmaxf(acc.x, 0.f); acc.y = fmaxf(acc.y, 0.f);
    acc.z = fmaxf(acc.z, 0.f); acc.w = fmaxf(acc.w, 0.f);
    const float4 hv = *(const float4*)(hh + (size_t)r * D_ + off);

    float c;
    if (FIRST) {
        const float4 g1 = *(const float4*)(gw + off);
        const float4 g2 = *(const float4*)(gw + D_ + off);
        float s = hv.x*g1.x + hv.y*g1.y + hv.z*g1.z + hv.w*g1.w
                + acc.x*g2.x + acc.y*g2.y + acc.z*g2.z + acc.w*g2.w;
        for (int o = 16; o; o >>= 1) s += __shfl_xor_sync(0xFFFFFFFFu, s, o);
        c = 1.f / (1.f + __expf(-(s + gb[0])));
        if (lane == 0) cf[u] = c;
    } else {
        c = cf[u];
    }
    const float om = 1.f - c;
    float4 o;
    o.x = c*hv.x + om*acc.x; o.y = c*hv.y + om*acc.y;
    o.z = c*hv.z + om*acc.z; o.w = c*hv.w + om*acc.w;

    if (!s1 && zsub0) {
        const float4 zs = *(const float4*)(zsub0 + (size_t)r * D_ + off);
        o.x -= zs.x; o.y -= zs.y; o.z -= zs.z; o.w -= zs.w;
    }
    float* outF = s1 ? outF1 : outF0;
    bf16*  outB = s1 ? outB1 : outB0;
    if (outF) *(float4*)(outF + (size_t)r * D_ + off) = o;
    if (outB) stz4(outB + (size_t)r * D_ + off, o);
}

// ============ tail ============
__global__ void sub_k(const float* __restrict__ z2, const float* __restrict__ z1,
                      float* __restrict__ o)
{
    const size_t i = (size_t)blockIdx.x * blockDim.x + threadIdx.x;
    float4 a = ((const float4*)z2)[i];
    float4 b = ((const float4*)z1)[i];
    ((float4*)o)[i] = make_float4(a.x-b.x, a.y-b.y, a.z-b.z, a.w-b.w);
}

__global__ void pool_k(const float* __restrict__ h, const float* __restrict__ valid,
                       float* __restrict__ pooled)
{
    const int b = blockIdx.x, d = threadIdx.x;
    float s = 0.f, vs = 0.f;
#pragma unroll 8
    for (int n = 0; n < N_; n++) {
        float v = valid[b * N_ + n];
        s += h[((size_t)b * N_ + n) * D_ + d] * v;
        vs += v;
    }
    pooled[b * D_ + d] = s / vs;
}

__global__ void mlp_k(const float* __restrict__ pooled,
                      const float* __restrict__ w0, const float* __restrict__ b0,
                      const float* __restrict__ w1, const float* __restrict__ b1,
                      const float* __restrict__ w2, const float* __restrict__ b2,
                      const float* __restrict__ w3, const float* __restrict__ b3,
                      float* __restrict__ out)
{
    __shared__ float a0[128], a1[128], red[4];
    const int b = blockIdx.x, t = threadIdx.x;
    a0[t] = pooled[b * 128 + t];
    __syncthreads();
    float s = 0.f;
    for (int i = 0; i < 128; i++) s += a0[i] * w0[t*128+i];
    a1[t] = fmaxf(s + b0[t], 0.f);
    __syncthreads();
    s = 0.f;
    for (int i = 0; i < 128; i++) s += a1[i] * w1[t*128+i];
    a0[t] = fmaxf(s + b1[t], 0.f);
    __syncthreads();
    s = 0.f;
    for (int i = 0; i < 128; i++) s += a0[i] * w2[t*128+i];
    a1[t] = fmaxf(s + b2[t], 0.f);
    __syncthreads();
    float p = a1[t] * w3[t];
    for (int o = 16; o; o >>= 1) p += __shfl_xor_sync(0xFFFFFFFFu, p, o);
    if ((t & 31) == 0) red[t >> 5] = p;
    __syncthreads();
    if (t == 0) {
        float tot = red[0] + red[1] + red[2] + red[3] + b3[0];
        out[b] = 1.f / (1.f + expf(-tot));
    }
}

extern "C" void kernel_launch(void* const* d_in, const int* in_sizes, int n_in,
                              void* d_out, int out_size)
{
    const float* x       = (const float*)d_in[0];
    const float* adj1    = (const float*)d_in[1];
    const float* adj2    = (const float*)d_in[2];
    const float* valid   = (const float*)d_in[3];
    const float* embede_w= (const float*)d_in[4];
    const float* gW      = (const float*)d_in[5];
    const float* gb      = (const float*)d_in[6];
    const float* gA      = (const float*)d_in[7];
    const float* gate_w  = (const float*)d_in[8];
    const float* gate_b  = (const float*)d_in[9];
    const float* fc0_w   = (const float*)d_in[10];
    const float* fc0_b   = (const float*)d_in[11];
    const float* fc1_w   = (const float*)d_in[12];
    const float* fc1_b   = (const float*)d_in[13];
    const float* fc2_w   = (const float*)d_in[14];
    const float* fc2_b   = (const float*)d_in[15];
    const float* fc3_w   = (const float*)d_in[16];
    const float* fc3_b   = (const float*)d_in[17];
    float* out = (float*)d_out;

    float *p_h, *p_hh, *p_hA, *p_zA, *p_zC, *p_cf, *p_pool, *p_invs;
    bf16 *p_hhb, *p_zb;
    float *p_ev, *p_av;
    int *p_rp, *p_col, *p_mir, *p_us;
    cudaGetSymbolAddress((void**)&p_h,   g_h);
    cudaGetSymbolAddress((void**)&p_hh,  g_hh);
    cudaGetSymbolAddress((void**)&p_hA,  g_hA);
    cudaGetSymbolAddress((void**)&p_hhb, g_hhb);
    cudaGetSymbolAddress((void**)&p_zb,  g_zb);
    cudaGetSymbolAddress((void**)&p_zA,  g_zA);
    cudaGetSymbolAddress((void**)&p_zC,  g_zC);
    cudaGetSymbolAddress((void**)&p_cf,  g_cf);
    cudaGetSymbolAddress((void**)&p_pool,g_pool);
    cudaGetSymbolAddress((void**)&p_ev,  g_ev);
    cudaGetSymbolAddress((void**)&p_av,  g_av);
    cudaGetSymbolAddress((void**)&p_invs,g_invs);
    cudaGetSymbolAddress((void**)&p_rp,  g_rowptr);
    cudaGetSymbolAddress((void**)&p_col, g_col);
    cudaGetSymbolAddress((void**)&p_mir, g_mir);
    cudaGetSymbolAddress((void**)&p_us,  g_us);

    const int NHOPS[4] = {1, 2, 3, 4};
    const float* adjs[2] = {adj1, adj2};
    int* rp_[2]   = {p_rp,  p_rp  + (BN_ + 1)};
    int* col_[2]  = {p_col, p_col + EMAX};
    int* mir_[2]  = {p_mir, p_mir + EMAX};
    int* us_[2]   = {p_us,  p_us  + BN_};
    float* ev_[2] = {p_ev,  p_ev  + EMAX};
    float* av_[2] = {p_av,  p_av  + EMAX};
    bf16* zb_[2][2] = {{p_zb,               p_zb + (size_t)BN_*D_},
                       {p_zb + 2*(size_t)BN_*D_, p_zb + 3*(size_t)BN_*D_}};

    for (int a = 0; a < 2; a++) {
        deg_k   <<<2048, 256>>>(adjs[a], rp_[a]);
        scan_k  <<<1, 1024>>>(rp_[a]);
        fill_k  <<<2048, 256>>>(adjs[a], rp_[a], col_[a]);
        mirror_k<<<2048, 256>>>(rp_[a], col_[a], mir_[a], us_[a]);
    }

    // h = x @ embede_w^T
    sgemm_k<true,false,false><<<dim3(1,256,1),256>>>(x, embede_w, p_h, nullptr,
        BN_, D_, D_, nullptr);

    for (int k = 0; k < L_; k++) {
        const float* Wk  = gW + (size_t)k * D_ * D_;
        const float* bk  = gb + (size_t)k * D_;
        const float* Ak  = gA + (size_t)k * D_ * D_;
        const float* gwk = gate_w + (size_t)k * 2 * D_;
        const float* gbk = gate_b + k;
        const int nhop = NHOPS[k];

        // hh, hA shared by both branches (adj-independent)
        sgemm_k<true,true,true><<<dim3(1,256,1),256>>>(p_h, Wk, p_hh, p_hhb,
            BN_, D_, D_, bk);
        sgemm_k<false,false,false><<<dim3(1,256,1),256>>>(p_hh, Ak, p_hA, nullptr,
            BN_, D_, D_, nullptr);

        elog2_k<<<dim3(N_, B_, 2), 128>>>(p_hh, p_hA,
            rp_[0], col_[0], mir_[0], us_[0], ev_[0],
            rp_[1], col_[1], mir_[1], us_[1], ev_[1]);
        stats2_k<<<4096, 256>>>(rp_[0], ev_[0], rp_[1], ev_[1], p_invs);
        fold2_k <<<4096, 256>>>(rp_[0], col_[0], ev_[0], av_[0],
                                rp_[1], col_[1], ev_[1], av_[1], p_invs);

        if (nhop == 1) {
            // branch0: z -> zA (fp32); branch1: z - zA -> h (fused sub)
            spmm2_k<true><<<2048, 256>>>(
                rp_[0], col_[0], av_[0], p_hhb,
                rp_[0], col_[0], av_[0], p_hhb,
                p_zA, nullptr, nullptr, nullptr,
                p_hh, p_cf, gwk, gbk, nullptr, BN_);
            spmm2_k<true><<<2048, 256>>>(
                rp_[1], col_[1], av_[1], p_hhb,
                rp_[1], col_[1], av_[1], p_hhb,
                p_h, nullptr, nullptr, nullptr,
                p_hh, p_cf + BN_, gwk, gbk, p_zA, BN_);
        } else {
            int cur = 0;
            spmm2_k<true><<<4096, 256>>>(
                rp_[0], col_[0], av_[0], p_hhb,
                rp_[1], col_[1], av_[1], p_hhb,
                nullptr, nullptr, zb_[0][cur], zb_[1][cur],
                p_hh, p_cf, gwk, gbk, nullptr, 2*BN_);
            for (int hp = 1; hp < nhop - 1; hp++) {
                spmm2_k<false><<<4096, 256>>>(
                    rp_[0], col_[0], av_[0], zb_[0][cur],
                    rp_[1], col_[1], av_[1], zb_[1][cur],
                    nullptr, nullptr, zb_[0][cur^1], zb_[1][cur^1],
                    p_hh, p_cf, nullptr, nullptr, nullptr, 2*BN_);
                cur ^= 1;
            }
            spmm2_k<false><<<4096, 256>>>(
                rp_[0], col_[0], av_[0], zb_[0][cur],
                rp_[1], col_[1], av_[1], zb_[1][cur],
                p_zA, p_zC, nullptr, nullptr,
                p_hh, p_cf, nullptr, nullptr, nullptr, 2*BN_);
            sub_k<<<2048, 256>>>(p_zC, p_zA, p_h);
        }
    }

    pool_k<<<B_, D_>>>(p_h, valid, p_pool);
    mlp_k<<<B_, D_>>>(p_pool, fc0_w, fc0_b, fc1_w, fc1_b,
                      fc2_w, fc2_b, fc3_w, fc3_b, out);
}

// round 11
// speedup vs baseline: 3.4186x; 1.0142x over previous
#include <cuda_runtime.h>
#include <cuda_bf16.h>
#include <math.h>

#define B_ 16
#define N_ 1024
#define D_ 128
#define L_ 4
#define BN_ (B_*N_)
#define EMAX (1<<22)

typedef __nv_bfloat16 bf16;
typedef __nv_bfloat162 bf162;

__device__ __align__(128) float g_h [BN_*D_];
__device__ __align__(128) float g_hh[BN_*D_];
__device__ __align__(128) float g_hA[BN_*D_];
__device__ __align__(128) bf16  g_hhb[BN_*D_];
__device__ __align__(128) bf16  g_hAb[BN_*D_];
__device__ __align__(128) bf16  g_zb[4][BN_*D_];
__device__ __align__(128) float g_zA[BN_*D_];
__device__ __align__(128) float g_zC[BN_*D_];
__device__ __align__(128) float g_cf[2*BN_];
__device__ __align__(128) float g_pool[B_*D_];
__device__ __align__(128) int   g_rowptr[2][BN_ + 1];
__device__ __align__(128) int   g_us[2][BN_];
__device__ __align__(128) int   g_col[2][EMAX];
__device__ __align__(128) int   g_mir[2][EMAX];
__device__ __align__(128) float g_ev[2][EMAX];
__device__ __align__(128) float g_av[2][EMAX];
__device__ __align__(128) float g_invs[2*BN_];

// ---------- bf16 helpers ----------
__device__ __forceinline__ float4 ldz4(const bf16* p) {
    uint2 raw = *(const uint2*)p;
    bf162 lo = *reinterpret_cast<bf162*>(&raw.x);
    bf162 hi = *reinterpret_cast<bf162*>(&raw.y);
    float2 f0 = __bfloat1622float2(lo);
    float2 f1 = __bfloat1622float2(hi);
    return make_float4(f0.x, f0.y, f1.x, f1.y);
}
__device__ __forceinline__ void stz4(bf16* p, float4 v) {
    bf162 a = __floats2bfloat162_rn(v.x, v.y);
    bf162 b = __floats2bfloat162_rn(v.z, v.w);
    uint2 r;
    r.x = *reinterpret_cast<unsigned*>(&a);
    r.y = *reinterpret_cast<unsigned*>(&b);
    *(uint2*)p = r;
}

// ============ embede SGEMM: 64x128 tile, 4x8/thread (TRANSB) ============
__global__ void __launch_bounds__(256)
sgemm_e_k(const float* __restrict__ Ag, const float* __restrict__ Bg,
          float* __restrict__ Cg, int K)
{
    __shared__ float As[16][68];
    __shared__ float Bs[16][132];
    const int tid = threadIdx.x;
    const int tx = tid & 15, ty = tid >> 4;
    const int mbase = blockIdx.x * 64;

    const int arow  = tid >> 2;
    const int akoff = (tid & 3) * 4;
    const float* aptr = Ag + (size_t)(mbase + arow) * K + akoff;
    const int bn = tid & 127, bkh = (tid >> 7) * 8;
    const float* bptr = Bg + (size_t)bn * K + bkh;

    float acc[4][8];
#pragma unroll
    for (int i = 0; i < 4; i++)
#pragma unroll
        for (int j = 0; j < 8; j++) acc[i][j] = 0.f;

    const int nk = K >> 4;
    for (int kc = 0; kc < nk; ++kc) {
        float4 pa  = *(const float4*)(aptr + kc * 16);
        float4 pb0 = *(const float4*)(bptr + kc * 16);
        float4 pb1 = *(const float4*)(bptr + kc * 16 + 4);
        As[akoff+0][arow]=pa.x; As[akoff+1][arow]=pa.y;
        As[akoff+2][arow]=pa.z; As[akoff+3][arow]=pa.w;
        Bs[bkh+0][bn]=pb0.x; Bs[bkh+1][bn]=pb0.y;
        Bs[bkh+2][bn]=pb0.z; Bs[bkh+3][bn]=pb0.w;
        Bs[bkh+4][bn]=pb1.x; Bs[bkh+5][bn]=pb1.y;
        Bs[bkh+6][bn]=pb1.z; Bs[bkh+7][bn]=pb1.w;
        __syncthreads();
#pragma unroll
        for (int kk = 0; kk < 16; ++kk) {
            float4 av0 = *(const float4*)&As[kk][ty*4];
            float4 bv0 = *(const float4*)&Bs[kk][tx*8];
            float4 bv1 = *(const float4*)&Bs[kk][tx*8+4];
            float ar[4] = {av0.x,av0.y,av0.z,av0.w};
            float br[8] = {bv0.x,bv0.y,bv0.z,bv0.w,bv1.x,bv1.y,bv1.z,bv1.w};
#pragma unroll
            for (int i = 0; i < 4; i++)
#pragma unroll
                for (int j = 0; j < 8; j++)
                    acc[i][j] += ar[i] * br[j];
        }
        __syncthreads();
    }
    const int row0 = mbase + ty * 4;
    const int col0 = tx * 8;
#pragma unroll
    for (int i = 0; i < 4; i++) {
        float4* cp = (float4*)(Cg + (size_t)(row0 + i) * D_ + col0);
        cp[0] = make_float4(acc[i][0], acc[i][1], acc[i][2], acc[i][3]);
        cp[1] = make_float4(acc[i][4], acc[i][5], acc[i][6], acc[i][7]);
    }
}

// ===== fused: hh = h@W^T + b (store f32+bf16), hA = hh@A (store f32+bf16) ===
__global__ void __launch_bounds__(256)
hhA_k(const float* __restrict__ h, const float* __restrict__ W,
      const float* __restrict__ A, const float* __restrict__ bias,
      float* __restrict__ hh, bf16* __restrict__ hhb,
      float* __restrict__ hA, bf16* __restrict__ hAb)
{
    __shared__ float As[16][68];
    __shared__ float Bs[16][132];
    __shared__ float hhs[64][132];
    const int tid = threadIdx.x;
    const int tx = tid & 15, ty = tid >> 4;
    const int mbase = blockIdx.x * 64;

    const int arow  = tid >> 2;
    const int akoff = (tid & 3) * 4;
    const float* aptr = h + (size_t)(mbase + arow) * D_ + akoff;
    const int bn = tid & 127, bkh = (tid >> 7) * 8;
    const float* wptr = W + (size_t)bn * D_ + bkh;

    float acc[4][8];
#pragma unroll
    for (int i = 0; i < 4; i++)
#pragma unroll
        for (int j = 0; j < 8; j++) acc[i][j] = 0.f;

    // phase 1: hh = h @ W^T
#pragma unroll 1
    for (int kc = 0; kc < 8; ++kc) {
        float4 pa  = *(const float4*)(aptr + kc * 16);
        float4 pb0 = *(const float4*)(wptr + kc * 16);
        float4 pb1 = *(const float4*)(wptr + kc * 16 + 4);
        As[akoff+0][arow]=pa.x; As[akoff+1][arow]=pa.y;
        As[akoff+2][arow]=pa.z; As[akoff+3][arow]=pa.w;
        Bs[bkh+0][bn]=pb0.x; Bs[bkh+1][bn]=pb0.y;
        Bs[bkh+2][bn]=pb0.z; Bs[bkh+3][bn]=pb0.w;
        Bs[bkh+4][bn]=pb1.x; Bs[bkh+5][bn]=pb1.y;
        Bs[bkh+6][bn]=pb1.z; Bs[bkh+7][bn]=pb1.w;
        __syncthreads();
#pragma unroll
        for (int kk = 0; kk < 16; ++kk) {
            float4 av0 = *(const float4*)&As[kk][ty*4];
            float4 bv0 = *(const float4*)&Bs[kk][tx*8];
            float4 bv1 = *(const float4*)&Bs[kk][tx*8+4];
            float ar[4] = {av0.x,av0.y,av0.z,av0.w};
            float br[8] = {bv0.x,bv0.y,bv0.z,bv0.w,bv1.x,bv1.y,bv1.z,bv1.w};
#pragma unroll
            for (int i = 0; i < 4; i++)
#pragma unroll
                for (int j = 0; j < 8; j++)
                    acc[i][j] += ar[i] * br[j];
        }
        __syncthreads();
    }

    // bias, park in smem, store hh
    const int row0 = ty * 4;
    const int col0 = tx * 8;
#pragma unroll
    for (int i = 0; i < 4; i++) {
        float o[8];
#pragma unroll
        for (int j = 0; j < 8; j++) {
            o[j] = acc[i][j] + bias[col0 + j];
            hhs[row0 + i][col0 + j] = o[j];
            acc[i][j] = 0.f;
        }
        const size_t go = (size_t)(mbase + row0 + i) * D_ + col0;
        *(float4*)(hh + go)     = make_float4(o[0], o[1], o[2], o[3]);
        *(float4*)(hh + go + 4) = make_float4(o[4], o[5], o[6], o[7]);
        stz4(hhb + go,     make_float4(o[0], o[1], o[2], o[3]));
        stz4(hhb + go + 4, make_float4(o[4], o[5], o[6], o[7]));
    }
    __syncthreads();

    // phase 2: hA = hhs @ A  (NN)
    const int bkr = tid >> 4, bcoff = (tid & 15) * 8;
#pragma unroll 1
    for (int kc = 0; kc < 8; ++kc) {
        const float* ap = A + (size_t)(kc * 16 + bkr) * D_ + bcoff;
        float4 pb0 = *(const float4*)ap;
        float4 pb1 = *(const float4*)(ap + 4);
        *(float4*)&Bs[bkr][bcoff]   = pb0;
        *(float4*)&Bs[bkr][bcoff+4] = pb1;
        __syncthreads();
#pragma unroll
        for (int kk = 0; kk < 16; ++kk) {
            float4 bv0 = *(const float4*)&Bs[kk][tx*8];
            float4 bv1 = *(const float4*)&Bs[kk][tx*8+4];
            float br[8] = {bv0.x,bv0.y,bv0.z,bv0.w,bv1.x,bv1.y,bv1.z,bv1.w};
#pragma unroll
            for (int i = 0; i < 4; i++) {
                const float a = hhs[row0 + i][kc * 16 + kk];
#pragma unroll
                for (int j = 0; j < 8; j++)
                    acc[i][j] += a * br[j];
            }
        }
        __syncthreads();
    }
#pragma unroll
    for (int i = 0; i < 4; i++) {
        const size_t go = (size_t)(mbase + row0 + i) * D_ + col0;
        *(float4*)(hA + go)     = make_float4(acc[i][0], acc[i][1], acc[i][2], acc[i][3]);
        *(float4*)(hA + go + 4) = make_float4(acc[i][4], acc[i][5], acc[i][6], acc[i][7]);
        stz4(hAb + go,     make_float4(acc[i][0], acc[i][1], acc[i][2], acc[i][3]));
        stz4(hAb + go + 4, make_float4(acc[i][4], acc[i][5], acc[i][6], acc[i][7]));
    }
}

// ============ CSR build (dual-adj via blockIdx.y) ============
__global__ void deg_k(const float* __restrict__ a0, const float* __restrict__ a1,
                      int* __restrict__ rp0, int* __restrict__ rp1)
{
    const float* adj = blockIdx.y ? a1 : a0;
    int* rp = blockIdx.y ? rp1 : rp0;
    const int wid = (blockIdx.x * blockDim.x + threadIdx.x) >> 5;
    const int lane = threadIdx.x & 31;
    if (wid >= BN_) return;
    const float* row = adj + (size_t)wid * N_;
    int c = 0;
#pragma unroll 4
    for (int k = 0; k < 32; k++) c += (row[lane + k * 32] > 0.f) ? 1 : 0;
    for (int o = 16; o; o >>= 1) c += __shfl_xor_sync(0xFFFFFFFFu, c, o);
    if (lane == 0) rp[wid + 1] = c;
}

__global__ void scan_k(int* __restrict__ rp0, int* __restrict__ rp1)
{
    int* rp = blockIdx.x ? rp1 : rp0;
    __shared__ int part[1024];
    const int t = threadIdx.x;
    int loc[16];
    int run = 0;
#pragma unroll
    for (int k = 0; k < 16; k++) { run += rp[1 + t * 16 + k]; loc[k] = run; }
    part[t] = run;
    __syncthreads();
    for (int off = 1; off < 1024; off <<= 1) {
        int v = (t >= off) ? part[t - off] : 0;
        __syncthreads();
        part[t] += v;
        __syncthreads();
    }
    const int excl = (t == 0) ? 0 : part[t - 1];
#pragma unroll
    for (int k = 0; k < 16; k++) rp[1 + t * 16 + k] = excl + loc[k];
    if (t == 0) rp[0] = 0;
}

__global__ void fill_k(const float* __restrict__ a0, const float* __restrict__ a1,
                       const int* __restrict__ rp0, const int* __restrict__ rp1,
                       int* __restrict__ col0, int* __restrict__ col1)
{
    const float* adj = blockIdx.y ? a1 : a0;
    const int* rp = blockIdx.y ? rp1 : rp0;
    int* col = blockIdx.y ? col1 : col0;
    const int wid = (blockIdx.x * blockDim.x + threadIdx.x) >> 5;
    const int lane = threadIdx.x & 31;
    if (wid >= BN_) return;
    const float* row = adj + (size_t)wid * N_;
    const int c0 = lane * 32;
    int cnt = 0;
#pragma unroll 4
    for (int k = 0; k < 32; k++) cnt += (row[c0 + k] > 0.f) ? 1 : 0;
    int inc = cnt;
    for (int off = 1; off < 32; off <<= 1) {
        int v = __shfl_up_sync(0xFFFFFFFFu, inc, off);
        if (lane >= off) inc += v;
    }
    int pos = rp[wid] + (inc - cnt);
    for (int k = 0; k < 32; k++)
        if (row[c0 + k] > 0.f) col[pos++] = c0 + k;
}

__global__ void mirror_k(const int* __restrict__ rp0, const int* __restrict__ col0,
                         int* __restrict__ mir0, int* __restrict__ us0,
                         const int* __restrict__ rp1, const int* __restrict__ col1,
                         int* __restrict__ mir1, int* __restrict__ us1)
{
    const int* rp  = blockIdx.y ? rp1  : rp0;
    const int* col = blockIdx.y ? col1 : col0;
    int* mir = blockIdx.y ? mir1 : mir0;
    int* us  = blockIdx.y ? us1  : us0;
    const int wid = (blockIdx.x * blockDim.x + threadIdx.x) >> 5;
    const int lane = threadIdx.x & 31;
    if (wid >= BN_) return;
    const int i = wid & (N_ - 1);
    const int bN = wid - i;
    const int rs = rp[wid], re = rp[wid + 1];
    for (int e = rs + lane; e < re; e += 32) {
        const int j = col[e];
        if (j == i) us[wid] = e;
        int lo = rp[bN + j], hi = rp[bN + j + 1];
        while (lo < hi) {
            int mid = (lo + hi) >> 1;
            if (col[mid] < i) lo = mid + 1; else hi = mid;
        }
        mir[e] = lo;
    }
}

// ===== edge logits: i-side fp32 smem, j-side bf16 gather, dual-branch ======
__global__ void __launch_bounds__(128)
elog2_k(const float* __restrict__ hh, const float* __restrict__ hA,
        const bf16* __restrict__ hhb, const bf16* __restrict__ hAb,
        const int* __restrict__ rp0, const int* __restrict__ col0,
        const int* __restrict__ mir0, const int* __restrict__ us0,
        float* __restrict__ ev0,
        const int* __restrict__ rp1, const int* __restrict__ col1,
        const int* __restrict__ mir1, const int* __restrict__ us1,
        float* __restrict__ ev1)
{
    const int br = blockIdx.z;
    const int* rp  = br ? rp1  : rp0;
    const int* col = br ? col1 : col0;
    const int* mir = br ? mir1 : mir0;
    const int* us  = br ? us1  : us0;
    float*     ev  = br ? ev1  : ev0;

    __shared__ float shh[128], sha[128];
    const int i = blockIdx.x, b = blockIdx.y;
    const int r = b * N_ + i;
    const int t = threadIdx.x;
    shh[t] = hh[(size_t)r * D_ + t];
    sha[t] = hA[(size_t)r * D_ + t];
    __syncthreads();
    const int w = t >> 5, lane = t & 31;
    const int rs = us[r], re = rp[r + 1];
    const float4 a1 = *(const float4*)(sha + lane * 4);
    const float4 h1 = *(const float4*)(shh + lane * 4);
    for (int e = rs + w; e < re; e += 4) {
        const int j = col[e];
        const size_t jo = ((size_t)(b * N_ + j)) * D_ + lane * 4;
        const float4 h2 = ldz4(hhb + jo);
        const float4 a2 = ldz4(hAb + jo);
        float p = a1.x*h2.x + a1.y*h2.y + a1.z*h2.z + a1.w*h2.w
                + h1.x*a2.x + h1.y*a2.y + h1.z*a2.z + h1.w*a2.w;
        for (int o = 16; o; o >>= 1) p += __shfl_xor_sync(0xFFFFFFFFu, p, o);
        if (lane == 0) {
            const float x = __expf(p);
            ev[e] = x;
            ev[mir[e]] = x;
        }
    }
}

// ===== softmax denominators, both branches =====
__global__ void stats2_k(const int* __restrict__ rp0, const float* __restrict__ ev0,
                         const int* __restrict__ rp1, const float* __restrict__ ev1,
                         float* __restrict__ invs)
{
    const int u = blockIdx.x * 8 + (threadIdx.x >> 5);
    const int lane = threadIdx.x & 31;
    if (u >= 2 * BN_) return;
    const bool s1 = (u >= BN_);
    const int r = s1 ? u - BN_ : u;
    const int* rp = s1 ? rp1 : rp0;
    const float* ev = s1 ? ev1 : ev0;
    const int rs = rp[r], re = rp[r + 1];
    float s = 0.f;
    for (int e = rs + lane; e < re; e += 32) s += ev[e];
    for (int o = 16; o; o >>= 1) s += __shfl_xor_sync(0xFFFFFFFFu, s, o);
    if (lane == 0) invs[u] = 1.f / (s + (float)(N_ - (re - rs)));
}

// ===== fold column normalizer, both branches =====
__global__ void fold2_k(const int* __restrict__ rp0, const int* __restrict__ col0,
                        const float* __restrict__ ev0, float* __restrict__ av0,
                        const int* __restrict__ rp1, const int* __restrict__ col1,
                        const float* __restrict__ ev1, float* __restrict__ av1,
                        const float* __restrict__ invs)
{
    const int u = blockIdx.x * 8 + (threadIdx.x >> 5);
    const int lane = threadIdx.x & 31;
    if (u >= 2 * BN_) return;
    const bool s1 = (u >= BN_);
    const int r = s1 ? u - BN_ : u;
    const int* rp  = s1 ? rp1  : rp0;
    const int* col = s1 ? col1 : col0;
    const float* ev = s1 ? ev1 : ev0;
    float* av = s1 ? av1 : av0;
    const int ibase = (s1 ? BN_ : 0) + (r & ~(N_ - 1));
    const int rs = rp[r], re = rp[r + 1];
    for (int e = rs + lane; e < re; e += 32)
        av[e] = ev[e] * invs[ibase + col[e]];
}

// ============ SpMM, bf16 gather, dual-branch ============
template<bool FIRST>
__global__ void __launch_bounds__(256)
spmm2_k(const int* __restrict__ rp0, const int* __restrict__ col0,
        const float* __restrict__ av0, const bf16* __restrict__ zs0,
        const int* __restrict__ rp1, const int* __restrict__ col1,
        const float* __restrict__ av1, const bf16* __restrict__ zs1,
        float* __restrict__ outF0, float* __restrict__ outF1,
        bf16* __restrict__ outB0, bf16* __restrict__ outB1,
        const float* __restrict__ hh, float* __restrict__ cf,
        const float* __restrict__ gw, const float* __restrict__ gb,
        const float* __restrict__ zsub0, int nrows)
{
    const int u = blockIdx.x * 8 + (threadIdx.x >> 5);
    const int lane = threadIdx.x & 31;
    if (u >= nrows) return;
    const bool s1 = (u >= BN_);
    const int r = s1 ? u - BN_ : u;
    const int* rp  = s1 ? rp1  : rp0;
    const int* col = s1 ? col1 : col0;
    const float* av = s1 ? av1 : av0;
    const bf16* zb = (s1 ? zs1 : zs0) + (size_t)(r & ~(N_ - 1)) * D_;
    const int rs = rp[r], re = rp[r + 1];
    const int off = lane * 4;

    float4 acc = make_float4(0.f, 0.f, 0.f, 0.f);
    int e = rs;
    for (; e + 4 <= re; e += 4) {
        const int   j0 = col[e],   j1 = col[e+1], j2 = col[e+2], j3 = col[e+3];
        const float a0 = av[e],    a1 = av[e+1],  a2 = av[e+2],  a3 = av[e+3];
        const float4 z0 = ldz4(zb + (size_t)j0 * D_ + off);
        const float4 z1 = ldz4(zb + (size_t)j1 * D_ + off);
        const float4 z2 = ldz4(zb + (size_t)j2 * D_ + off);
        const float4 z3 = ldz4(zb + (size_t)j3 * D_ + off);
        acc.x += a0*z0.x + a1*z1.x + a2*z2.x + a3*z3.x;
        acc.y += a0*z0.y + a1*z1.y + a2*z2.y + a3*z3.y;
        acc.z += a0*z0.z + a1*z1.z + a2*z2.z + a3*z3.z;
        acc.w += a0*z0.w + a1*z1.w + a2*z2.w + a3*z3.w;
    }
    for (; e < re; ++e) {
        const int j = col[e];
        const float a = av[e];
        const float4 zv = ldz4(zb + (size_t)j * D_ + off);
        acc.x += a*zv.x; acc.y += a*zv.y; acc.z += a*zv.z; acc.w += a*zv.w;
    }

    acc.x = fmaxf(acc.x, 0.f); acc.y = fmaxf(acc.y, 0.f);
    acc.z = fmaxf(acc.z, 0.f); acc.w = fmaxf(acc.w, 0.f);
    const float4 hv = *(const float4*)(hh + (size_t)r * D_ + off);

    float c;
    if (FIRST) {
        const float4 g1 = *(const float4*)(gw + off);
        const float4 g2 = *(const float4*)(gw + D_ + off);
        float s = hv.x*g1.x + hv.y*g1.y + hv.z*g1.z + hv.w*g1.w
                + acc.x*g2.x + acc.y*g2.y + acc.z*g2.z + acc.w*g2.w;
        for (int o = 16; o; o >>= 1) s += __shfl_xor_sync(0xFFFFFFFFu, s, o);
        c = 1.f / (1.f + __expf(-(s + gb[0])));
        if (lane == 0) cf[u] = c;
    } else {
        c = cf[u];
    }
    const float om = 1.f - c;
    float4 o;
    o.x = c*hv.x + om*acc.x; o.y = c*hv.y + om*acc.y;
    o.z = c*hv.z + om*acc.z; o.w = c*hv.w + om*acc.w;

    if (!s1 && zsub0) {
        const float4 zs = *(const float4*)(zsub0 + (size_t)r * D_ + off);
        o.x -= zs.x; o.y -= zs.y; o.z -= zs.z; o.w -= zs.w;
    }
    float* outF = s1 ? outF1 : outF0;
    bf16*  outB = s1 ? outB1 : outB0;
    if (outF) *(float4*)(outF + (size_t)r * D_ + off) = o;
    if (outB) stz4(outB + (size_t)r * D_ + off, o);
}

// ============ tail ============
__global__ void sub_k(const float* __restrict__ z2, const float* __restrict__ z1,
                      float* __restrict__ o)
{
    const size_t i = (size_t)blockIdx.x * blockDim.x + threadIdx.x;
    float4 a = ((const float4*)z2)[i];
    float4 b = ((const float4*)z1)[i];
    ((float4*)o)[i] = make_float4(a.x-b.x, a.y-b.y, a.z-b.z, a.w-b.w);
}

__global__ void pool_k(const float* __restrict__ h, const float* __restrict__ valid,
                       float* __restrict__ pooled)
{
    const int b = blockIdx.x, d = threadIdx.x;
    float s = 0.f, vs = 0.f;
#pragma unroll 8
    for (int n = 0; n < N_; n++) {
        float v = valid[b * N_ + n];
        s += h[((size_t)b * N_ + n) * D_ + d] * v;
        vs += v;
    }
    pooled[b * D_ + d] = s / vs;
}

__global__ void mlp_k(const float* __restrict__ pooled,
                      const float* __restrict__ w0, const float* __restrict__ b0,
                      const float* __restrict__ w1, const float* __restrict__ b1,
                      const float* __restrict__ w2, const float* __restrict__ b2,
                      const float* __restrict__ w3, const float* __restrict__ b3,
                      float* __restrict__ out)
{
    __shared__ float a0[128], a1[128], red[4];
    const int b = blockIdx.x, t = threadIdx.x;
    a0[t] = pooled[b * 128 + t];
    __syncthreads();
    float s = 0.f;
    for (int i = 0; i < 128; i++) s += a0[i] * w0[t*128+i];
    a1[t] = fmaxf(s + b0[t], 0.f);
    __syncthreads();
    s = 0.f;
    for (int i = 0; i < 128; i++) s += a1[i] * w1[t*128+i];
    a0[t] = fmaxf(s + b1[t], 0.f);
    __syncthreads();
    s = 0.f;
    for (int i = 0; i < 128; i++) s += a0[i] * w2[t*128+i];
    a1[t] = fmaxf(s + b2[t], 0.f);
    __syncthreads();
    float p = a1[t] * w3[t];
    for (int o = 16; o; o >>= 1) p += __shfl_xor_sync(0xFFFFFFFFu, p, o);
    if ((t & 31) == 0) red[t >> 5] = p;
    __syncthreads();
    if (t == 0) {
        float tot = red[0] + red[1] + red[2] + red[3] + b3[0];
        out[b] = 1.f / (1.f + expf(-tot));
    }
}

extern "C" void kernel_launch(void* const* d_in, const int* in_sizes, int n_in,
                              void* d_out, int out_size)
{
    const float* x       = (const float*)d_in[0];
    const float* adj1    = (const float*)d_in[1];
    const float* adj2    = (const float*)d_in[2];
    const float* valid   = (const float*)d_in[3];
    const float* embede_w= (const float*)d_in[4];
    const float* gW      = (const float*)d_in[5];
    const float* gb      = (const float*)d_in[6];
    const float* gA      = (const float*)d_in[7];
    const float* gate_w  = (const float*)d_in[8];
    const float* gate_b  = (const float*)d_in[9];
    const float* fc0_w   = (const float*)d_in[10];
    const float* fc0_b   = (const float*)d_in[11];
    const float* fc1_w   = (const float*)d_in[12];
    const float* fc1_b   = (const float*)d_in[13];
    const float* fc2_w   = (const float*)d_in[14];
    const float* fc2_b   = (const float*)d_in[15];
    const float* fc3_w   = (const float*)d_in[16];
    const float* fc3_b   = (const float*)d_in[17];
    float* out = (float*)d_out;

    float *p_h, *p_hh, *p_hA, *p_zA, *p_zC, *p_cf, *p_pool, *p_invs;
    bf16 *p_hhb, *p_hAb, *p_zb;
    float *p_ev, *p_av;
    int *p_rp, *p_col, *p_mir, *p_us;
    cudaGetSymbolAddress((void**)&p_h,   g_h);
    cudaGetSymbolAddress((void**)&p_hh,  g_hh);
    cudaGetSymbolAddress((void**)&p_hA,  g_hA);
    cudaGetSymbolAddress((void**)&p_hhb, g_hhb);
    cudaGetSymbolAddress((void**)&p_hAb, g_hAb);
    cudaGetSymbolAddress((void**)&p_zb,  g_zb);
    cudaGetSymbolAddress((void**)&p_zA,  g_zA);
    cudaGetSymbolAddress((void**)&p_zC,  g_zC);
    cudaGetSymbolAddress((void**)&p_cf,  g_cf);
    cudaGetSymbolAddress((void**)&p_pool,g_pool);
    cudaGetSymbolAddress((void**)&p_ev,  g_ev);
    cudaGetSymbolAddress((void**)&p_av,  g_av);
    cudaGetSymbolAddress((void**)&p_invs,g_invs);
    cudaGetSymbolAddress((void**)&p_rp,  g_rowptr);
    cudaGetSymbolAddress((void**)&p_col, g_col);
    cudaGetSymbolAddress((void**)&p_mir, g_mir);
    cudaGetSymbolAddress((void**)&p_us,  g_us);

    const int NHOPS[4] = {1, 2, 3, 4};
    int* rp_[2]   = {p_rp,  p_rp  + (BN_ + 1)};
    int* col_[2]  = {p_col, p_col + EMAX};
    int* mir_[2]  = {p_mir, p_mir + EMAX};
    int* us_[2]   = {p_us,  p_us  + BN_};
    float* ev_[2] = {p_ev,  p_ev  + EMAX};
    float* av_[2] = {p_av,  p_av  + EMAX};
    bf16* zb_[2][2] = {{p_zb,                    p_zb + (size_t)BN_*D_},
                       {p_zb + 2*(size_t)BN_*D_, p_zb + 3*(size_t)BN_*D_}};

    deg_k   <<<dim3(2048,2), 256>>>(adj1, adj2, rp_[0], rp_[1]);
    scan_k  <<<2, 1024>>>(rp_[0], rp_[1]);
    fill_k  <<<dim3(2048,2), 256>>>(adj1, adj2, rp_[0], rp_[1], col_[0], col_[1]);
    mirror_k<<<dim3(2048,2), 256>>>(rp_[0], col_[0], mir_[0], us_[0],
                                    rp_[1], col_[1], mir_[1], us_[1]);

    // h = x @ embede_w^T
    sgemm_e_k<<<256, 256>>>(x, embede_w, p_h, D_);

    for (int k = 0; k < L_; k++) {
        const float* Wk  = gW + (size_t)k * D_ * D_;
        const float* bk  = gb + (size_t)k * D_;
        const float* Ak  = gA + (size_t)k * D_ * D_;
        const float* gwk = gate_w + (size_t)k * 2 * D_;
        const float* gbk = gate_b + k;
        const int nhop = NHOPS[k];

        // fused hh & hA (shared by both branches)
        hhA_k<<<256, 256>>>(p_h, Wk, Ak, bk, p_hh, p_hhb, p_hA, p_hAb);

        elog2_k<<<dim3(N_, B_, 2), 128>>>(p_hh, p_hA, p_hhb, p_hAb,
            rp_[0], col_[0], mir_[0], us_[0], ev_[0],
            rp_[1], col_[1], mir_[1], us_[1], ev_[1]);
        stats2_k<<<4096, 256>>>(rp_[0], ev_[0], rp_[1], ev_[1], p_invs);
        fold2_k <<<4096, 256>>>(rp_[0], col_[0], ev_[0], av_[0],
                                rp_[1], col_[1], ev_[1], av_[1], p_invs);

        if (nhop == 1) {
            spmm2_k<true><<<2048, 256>>>(
                rp_[0], col_[0], av_[0], p_hhb,
                rp_[0], col_[0], av_[0], p_hhb,
                p_zA, nullptr, nullptr, nullptr,
                p_hh, p_cf, gwk, gbk, nullptr, BN_);
            spmm2_k<true><<<2048, 256>>>(
                rp_[1], col_[1], av_[1], p_hhb,
                rp_[1], col_[1], av_[1], p_hhb,
                p_h, nullptr, nullptr, nullptr,
                p_hh, p_cf + BN_, gwk, gbk, p_zA, BN_);
        } else {
            int cur = 0;
            spmm2_k<true><<<4096, 256>>>(
                rp_[0], col_[0], av_[0], p_hhb,
                rp_[1], col_[1], av_[1], p_hhb,
                nullptr, nullptr, zb_[0][cur], zb_[1][cur],
                p_hh, p_cf, gwk, gbk, nullptr, 2*BN_);
            for (int hp = 1; hp < nhop - 1; hp++) {
                spmm2_k<false><<<4096, 256>>>(
                    rp_[0], col_[0], av_[0], zb_[0][cur],
                    rp_[1], col_[1], av_[1], zb_[1][cur],
                    nullptr, nullptr, zb_[0][cur^1], zb_[1][cur^1],
                    p_hh, p_cf, nullptr, nullptr, nullptr, 2*BN_);
                cur ^= 1;
            }
            spmm2_k<false><<<4096, 256>>>(
                rp_[0], col_[0], av_[0], zb_[0][cur],
                rp_[1], col_[1], av_[1], zb_[1][cur],
                p_zA, p_zC, nullptr, nullptr,
                p_hh, p_cf, nullptr, nullptr, nullptr, 2*BN_);
            sub_k<<<2048, 256>>>(p_zC, p_zA, p_h);
        }
    }

    pool_k<<<B_, D_>>>(p_h, valid, p_pool);
    mlp_k<<<B_, D_>>>(p_pool, fc0_w, fc0_b, fc1_w, fc1_b,
                      fc2_w, fc2_b, fc3_w, fc3_b, out);
}